// round 2
// baseline (speedup 1.0000x reference)
#include <cuda_runtime.h>
#include <math.h>

// Problem constants
#define BATCH 4
#define SEQ   4096
#define CH    768
#define NHEAD 12
#define HDIM  64
#define M_ROWS (BATCH * SEQ)          // 16384
#define QKV_N  (3 * CH)               // 2304
#define BNC   (M_ROWS * CH)           // 12582912
#define SCALE 0.125f                  // 64^-0.5
#define EPSV  1e-10f

// ---------------- scratch (device globals; no allocation allowed) ----------
__device__ float g_qkv[M_ROWS * QKV_N];     // 151 MB: q|k|v rows (delu applied to q,k)
__device__ float g_attnL[M_ROWS * CH];      // 50 MB
__device__ float g_attnG[M_ROWS * CH];      // 50 MB
__device__ float g_red[3 * BATCH * CH];     // [kv_diag_raw | lkv_diag_raw | ksum_raw]

// ---------------- delu ----------------
__device__ __forceinline__ float delu_f(float x) {
    // p*relu(x) + exp(p*min(x,0)); p = 10
    return (x >= 0.0f) ? fmaf(10.0f, x, 1.0f) : __expf(10.0f * x);
}

// ---------------- SGEMM: C[M,Nn] = A[M,K] * B[Nn,K]^T (+bias) (+delu) -----
#define BM 128
#define BN 128
#define BKK 8
#define TM 8
#define TN 8

template <bool DO_DELU, bool DO_BIAS>
__global__ void __launch_bounds__(256)
sgemm_abT(const float* __restrict__ A, const float* __restrict__ B,
          const float* __restrict__ bias, float* __restrict__ C,
          int M, int Nn, int K, int delu_limit)
{
    __shared__ float As[BKK][BM];
    __shared__ float Bs[BKK][BN];

    const int tid = threadIdx.x;
    const int tx  = tid & 15;      // 0..15 col group
    const int ty  = tid >> 4;      // 0..15 row group
    const int m0  = blockIdx.y * BM;
    const int n0  = blockIdx.x * BN;

    const int lrow = tid >> 1;           // 0..127
    const int lcol = (tid & 1) * 4;      // 0 or 4

    const float* Aptr = A + (long)(m0 + lrow) * K + lcol;
    const float* Bptr = B + (long)(n0 + lrow) * K + lcol;

    float acc[TM][TN];
#pragma unroll
    for (int i = 0; i < TM; i++)
#pragma unroll
        for (int j = 0; j < TN; j++) acc[i][j] = 0.0f;

    float4 av = *reinterpret_cast<const float4*>(Aptr);
    float4 bv = *reinterpret_cast<const float4*>(Bptr);

    for (int k0 = 0; k0 < K; k0 += BKK) {
        As[lcol + 0][lrow] = av.x; As[lcol + 1][lrow] = av.y;
        As[lcol + 2][lrow] = av.z; As[lcol + 3][lrow] = av.w;
        Bs[lcol + 0][lrow] = bv.x; Bs[lcol + 1][lrow] = bv.y;
        Bs[lcol + 2][lrow] = bv.z; Bs[lcol + 3][lrow] = bv.w;
        __syncthreads();

        // prefetch next tile while computing
        float4 av2 = make_float4(0.f, 0.f, 0.f, 0.f);
        float4 bv2 = make_float4(0.f, 0.f, 0.f, 0.f);
        if (k0 + BKK < K) {
            av2 = *reinterpret_cast<const float4*>(Aptr + k0 + BKK);
            bv2 = *reinterpret_cast<const float4*>(Bptr + k0 + BKK);
        }

        float ar[TM], br[TN];
#pragma unroll
        for (int kk = 0; kk < BKK; kk++) {
#pragma unroll
            for (int i = 0; i < TM; i++) ar[i] = As[kk][ty * TM + i];
#pragma unroll
            for (int j = 0; j < TN; j++) br[j] = Bs[kk][tx * TN + j];
#pragma unroll
            for (int i = 0; i < TM; i++)
#pragma unroll
                for (int j = 0; j < TN; j++)
                    acc[i][j] = fmaf(ar[i], br[j], acc[i][j]);
        }
        __syncthreads();
        av = av2; bv = bv2;
    }

#pragma unroll
    for (int i = 0; i < TM; i++) {
        const int row = m0 + ty * TM + i;
#pragma unroll
        for (int j = 0; j < TN; j++) {
            const int col = n0 + tx * TN + j;
            float v = acc[i][j];
            if (DO_BIAS) v += bias[col];
            if (DO_DELU && col < delu_limit) v = delu_f(v);
            C[(long)row * Nn + col] = v;
        }
    }
}

// ---------------- zero the reduction accumulators --------------------------
__global__ void zero_red_kernel(float* __restrict__ red) {
    int i = blockIdx.x * blockDim.x + threadIdx.x;
    if (i < 3 * BATCH * CH) red[i] = 0.0f;
}

// ---------------- reductions over N per (b,h,d) ----------------------------
// red[0]: sum_n k*v ; red[1]: sum_n delu(y)*v ; red[2]: sum_n k
#define NCHUNKS 8
__global__ void __launch_bounds__(256)
reduce_kernel(const float* __restrict__ qkv, const float* __restrict__ y,
              float* __restrict__ red)
{
    const int bh  = blockIdx.x;            // 0..47
    const int b   = bh / NHEAD;
    const int h   = bh % NHEAD;
    const int tid = threadIdx.x;
    const int d   = tid & 63;
    const int sub = tid >> 6;              // 0..3
    const int nper = SEQ / NCHUNKS;        // 512
    const int n0 = blockIdx.y * nper;

    const int colk = CH + h * HDIM + d;    // k block
    const int colv = 2 * CH + h * HDIM + d;
    const int coly = h * HDIM + d;

    float akv = 0.f, alkv = 0.f, aks = 0.f;
    for (int n = n0 + sub; n < n0 + nper; n += 4) {
        const long r = (long)b * SEQ + n;
        const float kv_ = qkv[r * QKV_N + colk];
        const float vv  = qkv[r * QKV_N + colv];
        const float lk  = delu_f(y[r * CH + coly]);
        akv  = fmaf(kv_, vv, akv);
        alkv = fmaf(lk,  vv, alkv);
        aks += kv_;
    }

    __shared__ float s[3][256];
    s[0][tid] = akv; s[1][tid] = alkv; s[2][tid] = aks;
    __syncthreads();
    if (sub == 0) {
        const int o = b * CH + h * HDIM + d;
        float r0 = s[0][d] + s[0][64 + d] + s[0][128 + d] + s[0][192 + d];
        float r1 = s[1][d] + s[1][64 + d] + s[1][128 + d] + s[1][192 + d];
        float r2 = s[2][d] + s[2][64 + d] + s[2][128 + d] + s[2][192 + d];
        atomicAdd(&red[o], r0);
        atomicAdd(&red[BATCH * CH + o], r1);
        atomicAdd(&red[2 * BATCH * CH + o], r2);
    }
}

// ---------------- norm + attn elementwise ----------------------------------
__global__ void __launch_bounds__(768)
attn_kernel(const float* __restrict__ qkv, const float* __restrict__ red,
            float* __restrict__ outL, float* __restrict__ outG)
{
    const int bn = blockIdx.x;             // 0..16383
    const int b  = bn >> 12;               // / 4096
    const int c  = threadIdx.x;            // 0..767
    const int h  = c >> 6;

    const float q  = qkv[(long)bn * QKV_N + c];
    const float ks = red[2 * BATCH * CH + b * CH + c] + EPSV;
    float p = q * ks;
#pragma unroll
    for (int off = 16; off; off >>= 1)
        p += __shfl_down_sync(0xffffffffu, p, off);

    __shared__ float ws[24];
    const int warp = c >> 5;
    if ((c & 31) == 0) ws[warp] = p;
    __syncthreads();

    const float norm = 1.0f / (ws[2 * h] + ws[2 * h + 1]);
    const float kvd  = red[b * CH + c] * SCALE;
    const float lkvd = red[BATCH * CH + b * CH + c] * SCALE;

    outL[(long)bn * CH + c] = q * kvd  * norm;
    outG[(long)bn * CH + c] = q * lkvd * norm;
}

// ---------------- launch ---------------------------------------------------
extern "C" void kernel_launch(void* const* d_in, const int* in_sizes, int n_in,
                              void* d_out, int out_size)
{
    const float* x       = (const float*)d_in[0];
    const float* y       = (const float*)d_in[1];
    const float* qkv_w   = (const float*)d_in[2];
    const float* proj1_w = (const float*)d_in[3];
    const float* proj1_b = (const float*)d_in[4];
    const float* proj2_w = (const float*)d_in[5];
    const float* proj2_b = (const float*)d_in[6];
    float* out = (float*)d_out;

    float *qkv_p, *attnL_p, *attnG_p, *red_p;
    cudaGetSymbolAddress((void**)&qkv_p,   g_qkv);
    cudaGetSymbolAddress((void**)&attnL_p, g_attnL);
    cudaGetSymbolAddress((void**)&attnG_p, g_attnG);
    cudaGetSymbolAddress((void**)&red_p,   g_red);

    // 1) qkv = x @ qkv_w^T with delu fused on q,k columns
    {
        dim3 grid(QKV_N / BN, M_ROWS / BM);
        sgemm_abT<true, false><<<grid, 256>>>(x, qkv_w, nullptr, qkv_p,
                                              M_ROWS, QKV_N, CH, 2 * CH);
    }

    // 2) zero accumulators, then reductions over N
    zero_red_kernel<<<(3 * BATCH * CH + 255) / 256, 256>>>(red_p);
    {
        dim3 grid(BATCH * NHEAD, NCHUNKS);
        reduce_kernel<<<grid, 256>>>(qkv_p, y, red_p);
    }

    // 3) norm + elementwise attention outputs
    attn_kernel<<<M_ROWS, 768>>>(qkv_p, red_p, attnL_p, attnG_p);

    // 4) output projections (+bias) straight into d_out
    {
        dim3 grid(CH / BN, M_ROWS / BM);
        sgemm_abT<false, true><<<grid, 256>>>(attnL_p, proj1_w, proj1_b, out,
                                              M_ROWS, CH, CH, 0);
        sgemm_abT<false, true><<<grid, 256>>>(attnG_p, proj2_w, proj2_b, out + BNC,
                                              M_ROWS, CH, CH, 0);
    }
}

// round 4
// speedup vs baseline: 2.5413x; 2.5413x over previous
#include <cuda_runtime.h>
#include <cuda_bf16.h>
#include <cstdint>
#include <math.h>

// ---------------- problem constants ----------------
#define BATCH 4
#define SEQ   4096
#define CH    768
#define NHEAD 12
#define HDIM  64
#define M_ROWS (BATCH * SEQ)          // 16384
#define QKV_N  (3 * CH)               // 2304
#define BNC   (M_ROWS * CH)
#define SCALE 0.125f
#define EPSV  1e-10f
#define KDIM  768

// ---------------- scratch (device globals) ----------------
__device__ float g_qkv[M_ROWS * QKV_N];
__device__ __nv_bfloat16 g_xhi[M_ROWS * CH], g_xlo[M_ROWS * CH];
__device__ __nv_bfloat16 g_wqhi[QKV_N * CH], g_wqlo[QKV_N * CH];
__device__ __nv_bfloat16 g_w1hi[CH * CH],   g_w1lo[CH * CH];
__device__ __nv_bfloat16 g_w2hi[CH * CH],   g_w2lo[CH * CH];
__device__ __nv_bfloat16 g_aLhi[M_ROWS * CH], g_aLlo[M_ROWS * CH];
__device__ __nv_bfloat16 g_aGhi[M_ROWS * CH], g_aGlo[M_ROWS * CH];
__device__ float g_red[3 * BATCH * CH];

// ---------------- helpers ----------------
__device__ __forceinline__ float delu_f(float x) {
    return (x >= 0.0f) ? fmaf(10.0f, x, 1.0f) : __expf(10.0f * x);
}

__device__ __forceinline__ uint32_t smem_u32(const void* p) {
    uint32_t a;
    asm("{ .reg .u64 t; cvta.to.shared.u64 t, %1; cvt.u32.u64 %0, t; }" : "=r"(a) : "l"(p));
    return a;
}

__device__ __forceinline__ void cp16(uint32_t s, const void* g) {
    asm volatile("cp.async.cg.shared.global [%0], [%1], 16;" :: "r"(s), "l"(g));
}
#define CP_COMMIT() asm volatile("cp.async.commit_group;" ::: "memory")

__device__ __forceinline__ void ldsm4(uint32_t* r, uint32_t a) {
    asm volatile("ldmatrix.sync.aligned.m8n8.x4.shared.b16 {%0,%1,%2,%3}, [%4];"
                 : "=r"(r[0]), "=r"(r[1]), "=r"(r[2]), "=r"(r[3]) : "r"(a));
}

__device__ __forceinline__ void mma16816(float* c, const uint32_t* a, const uint32_t* b) {
    asm volatile(
        "mma.sync.aligned.m16n8k16.row.col.f32.bf16.bf16.f32 "
        "{%0,%1,%2,%3},{%4,%5,%6,%7},{%8,%9},{%0,%1,%2,%3};"
        : "+f"(c[0]), "+f"(c[1]), "+f"(c[2]), "+f"(c[3])
        : "r"(a[0]), "r"(a[1]), "r"(a[2]), "r"(a[3]), "r"(b[0]), "r"(b[1]));
}

// ---------------- split-bf16 HMMA GEMM ----------------
// C[M,Nn] = A[M,768] @ B[Nn,768]^T, A/B given as bf16 hi/lo pairs.
// 3 MMA passes: Ahi*Bhi + Alo*Bhi + Ahi*Blo, fp32 accumulate.
// Tile 128x128, BK=64, 256 threads (8 warps, warp tile 64x32), 2-stage cp.async.
#define BMt 128
#define BNt 128
#define BKt 64
#define NKT (KDIM / BKt)             // 12
#define STG 65536                    // bytes per stage (4 tiles x 16KB)
#define OFF_ALO 16384
#define OFF_BHI 32768
#define OFF_BLO 49152
#define GEMM_SMEM (2 * STG + 128)

template <bool DELU, bool BIAS>
__global__ void __launch_bounds__(256, 1)
gemm_mma(const __nv_bfloat16* __restrict__ Ahi, const __nv_bfloat16* __restrict__ Alo,
         const __nv_bfloat16* __restrict__ Bhi, const __nv_bfloat16* __restrict__ Blo,
         const float* __restrict__ bias, float* __restrict__ C,
         int Nn, int delu_limit)
{
    extern __shared__ char smraw[];
    const uint32_t sbase = (smem_u32(smraw) + 127u) & ~127u;
    const int tid  = threadIdx.x;
    const int lane = tid & 31, wid = tid >> 5;
    const int warp_m = wid >> 2, warp_n = wid & 3;     // 2 x 4 warps
    const int m0 = blockIdx.y * BMt, n0 = blockIdx.x * BNt;

    float acc[4][4][4];
#pragma unroll
    for (int i = 0; i < 4; i++)
#pragma unroll
        for (int j = 0; j < 4; j++)
#pragma unroll
            for (int e = 0; e < 4; e++) acc[i][j][e] = 0.0f;

    auto load_tile = [&](int kt, int s) {
        const uint32_t st = sbase + s * STG;
        const int kb = kt * BKt;
#pragma unroll
        for (int i = tid; i < 1024; i += 256) {
            const int r = i >> 3, cc = i & 7;
            uint32_t off = (uint32_t)(r * 128 + cc * 16);
            off ^= (off >> 3) & 0x70;
            const size_t ga = (size_t)(m0 + r) * KDIM + kb + cc * 8;
            const size_t gb = (size_t)(n0 + r) * KDIM + kb + cc * 8;
            cp16(st + off,           Ahi + ga);
            cp16(st + OFF_ALO + off, Alo + ga);
            cp16(st + OFF_BHI + off, Bhi + gb);
            cp16(st + OFF_BLO + off, Blo + gb);
        }
        CP_COMMIT();
    };

    load_tile(0, 0);

    // per-lane ldmatrix row-byte bases (before swizzle)
    const uint32_t arow = (uint32_t)((warp_m * 64 + (lane & 15)) * 128 + (lane >> 4) * 16);
    const uint32_t brow = (uint32_t)((warp_n * 32 + (lane & 15)) * 128 + (lane >> 4) * 16);

    for (int c = 0; c < NKT; c++) {
        const int s = c & 1;
        if (c + 1 < NKT) load_tile(c + 1, s ^ 1);
        if (c + 1 < NKT) asm volatile("cp.async.wait_group 1;" ::: "memory");
        else             asm volatile("cp.async.wait_group 0;" ::: "memory");
        __syncthreads();

        const uint32_t st = sbase + s * STG;
#pragma unroll
        for (int ks = 0; ks < 4; ks++) {
            const uint32_t kofs = ks * 32;
            uint32_t ah[4][4], al[4][4], bh[4][2], bl[4][2];
#pragma unroll
            for (int mf = 0; mf < 4; mf++) {
                uint32_t off = arow + mf * 2048 + kofs;
                off ^= (off >> 3) & 0x70;
                ldsm4(ah[mf], st + off);
                ldsm4(al[mf], st + OFF_ALO + off);
            }
#pragma unroll
            for (int g = 0; g < 2; g++) {
                uint32_t off = brow + g * 2048 + kofs;
                off ^= (off >> 3) & 0x70;
                uint32_t q[4];
                ldsm4(q, st + OFF_BHI + off);
                bh[g * 2][0] = q[0]; bh[g * 2][1] = q[2];
                bh[g * 2 + 1][0] = q[1]; bh[g * 2 + 1][1] = q[3];
                ldsm4(q, st + OFF_BLO + off);
                bl[g * 2][0] = q[0]; bl[g * 2][1] = q[2];
                bl[g * 2 + 1][0] = q[1]; bl[g * 2 + 1][1] = q[3];
            }
#pragma unroll
            for (int mf = 0; mf < 4; mf++)
#pragma unroll
                for (int nf = 0; nf < 4; nf++) {
                    mma16816(acc[mf][nf], ah[mf], bh[nf]);
                    mma16816(acc[mf][nf], al[mf], bh[nf]);
                    mma16816(acc[mf][nf], ah[mf], bl[nf]);
                }
        }
        __syncthreads();
    }

    // ---- epilogue ----
#pragma unroll
    for (int mf = 0; mf < 4; mf++) {
        const int row = m0 + warp_m * 64 + mf * 16 + (lane >> 2);
#pragma unroll
        for (int nf = 0; nf < 4; nf++) {
            const int col = n0 + warp_n * 32 + nf * 8 + (lane & 3) * 2;
            float v0 = acc[mf][nf][0], v1 = acc[mf][nf][1];
            float v2 = acc[mf][nf][2], v3 = acc[mf][nf][3];
            if (BIAS) {
                const float b0 = bias[col], b1 = bias[col + 1];
                v0 += b0; v1 += b1; v2 += b0; v3 += b1;
            }
            if (DELU && col < delu_limit) {
                v0 = delu_f(v0); v1 = delu_f(v1); v2 = delu_f(v2); v3 = delu_f(v3);
            }
            float2* p0 = reinterpret_cast<float2*>(C + (size_t)row * Nn + col);
            float2* p1 = reinterpret_cast<float2*>(C + (size_t)(row + 8) * Nn + col);
            *p0 = make_float2(v0, v1);
            *p1 = make_float2(v2, v3);
        }
    }
}

// ---------------- f32 -> bf16 hi/lo split ----------------
__global__ void split_kernel(const float* __restrict__ src,
                             __nv_bfloat16* __restrict__ hi,
                             __nv_bfloat16* __restrict__ lo, int n)
{
    int i = (blockIdx.x * blockDim.x + threadIdx.x) * 4;
    if (i >= n) return;
    float4 v = *reinterpret_cast<const float4*>(src + i);
    __nv_bfloat16 h0 = __float2bfloat16(v.x), h1 = __float2bfloat16(v.y);
    __nv_bfloat16 h2 = __float2bfloat16(v.z), h3 = __float2bfloat16(v.w);
    __nv_bfloat16 l0 = __float2bfloat16(v.x - __bfloat162float(h0));
    __nv_bfloat16 l1 = __float2bfloat16(v.y - __bfloat162float(h1));
    __nv_bfloat16 l2 = __float2bfloat16(v.z - __bfloat162float(h2));
    __nv_bfloat16 l3 = __float2bfloat16(v.w - __bfloat162float(h3));
    __nv_bfloat162* H = reinterpret_cast<__nv_bfloat162*>(hi + i);
    __nv_bfloat162* L = reinterpret_cast<__nv_bfloat162*>(lo + i);
    H[0] = __nv_bfloat162(h0, h1); H[1] = __nv_bfloat162(h2, h3);
    L[0] = __nv_bfloat162(l0, l1); L[1] = __nv_bfloat162(l2, l3);
}

// ---------------- zero reduction accumulators ----------------
__global__ void zero_red_kernel(float* __restrict__ red) {
    int i = blockIdx.x * blockDim.x + threadIdx.x;
    if (i < 3 * BATCH * CH) red[i] = 0.0f;
}

// ---------------- reductions over N per (b,h,d) ----------------
#define NCHUNKS 8
__global__ void __launch_bounds__(256)
reduce_kernel(const float* __restrict__ qkv, const float* __restrict__ y,
              float* __restrict__ red)
{
    const int bh  = blockIdx.x;
    const int b   = bh / NHEAD;
    const int h   = bh % NHEAD;
    const int tid = threadIdx.x;
    const int d   = tid & 63;
    const int sub = tid >> 6;
    const int nper = SEQ / NCHUNKS;
    const int n0 = blockIdx.y * nper;

    const int colk = CH + h * HDIM + d;
    const int colv = 2 * CH + h * HDIM + d;
    const int coly = h * HDIM + d;

    float akv = 0.f, alkv = 0.f, aks = 0.f;
    for (int n = n0 + sub; n < n0 + nper; n += 4) {
        const long r = (long)b * SEQ + n;
        const float kv_ = qkv[r * QKV_N + colk];
        const float vv  = qkv[r * QKV_N + colv];
        const float lk  = delu_f(y[r * CH + coly]);
        akv  = fmaf(kv_, vv, akv);
        alkv = fmaf(lk,  vv, alkv);
        aks += kv_;
    }

    __shared__ float s[3][256];
    s[0][tid] = akv; s[1][tid] = alkv; s[2][tid] = aks;
    __syncthreads();
    if (sub == 0) {
        const int o = b * CH + h * HDIM + d;
        float r0 = s[0][d] + s[0][64 + d] + s[0][128 + d] + s[0][192 + d];
        float r1 = s[1][d] + s[1][64 + d] + s[1][128 + d] + s[1][192 + d];
        float r2 = s[2][d] + s[2][64 + d] + s[2][128 + d] + s[2][192 + d];
        atomicAdd(&red[o], r0);
        atomicAdd(&red[BATCH * CH + o], r1);
        atomicAdd(&red[2 * BATCH * CH + o], r2);
    }
}

// ---------------- norm + attn elementwise -> bf16 hi/lo ----------------
__global__ void __launch_bounds__(768)
attn_kernel(const float* __restrict__ qkv, const float* __restrict__ red,
            __nv_bfloat16* __restrict__ oLh, __nv_bfloat16* __restrict__ oLl,
            __nv_bfloat16* __restrict__ oGh, __nv_bfloat16* __restrict__ oGl)
{
    const int bn = blockIdx.x;
    const int b  = bn >> 12;
    const int c  = threadIdx.x;
    const int h  = c >> 6;

    const float q  = qkv[(long)bn * QKV_N + c];
    const float ks = red[2 * BATCH * CH + b * CH + c] + EPSV;
    float p = q * ks;
#pragma unroll
    for (int off = 16; off; off >>= 1)
        p += __shfl_down_sync(0xffffffffu, p, off);

    __shared__ float ws[24];
    const int warp = c >> 5;
    if ((c & 31) == 0) ws[warp] = p;
    __syncthreads();

    const float norm = 1.0f / (ws[2 * h] + ws[2 * h + 1]);
    const float kvd  = red[b * CH + c] * SCALE;
    const float lkvd = red[BATCH * CH + b * CH + c] * SCALE;

    const float aL = q * kvd  * norm;
    const float aG = q * lkvd * norm;
    const size_t idx = (size_t)bn * CH + c;
    __nv_bfloat16 hL = __float2bfloat16(aL);
    __nv_bfloat16 hG = __float2bfloat16(aG);
    oLh[idx] = hL; oLl[idx] = __float2bfloat16(aL - __bfloat162float(hL));
    oGh[idx] = hG; oGl[idx] = __float2bfloat16(aG - __bfloat162float(hG));
}

// ---------------- launch ----------------
extern "C" void kernel_launch(void* const* d_in, const int* in_sizes, int n_in,
                              void* d_out, int out_size)
{
    const float* x       = (const float*)d_in[0];
    const float* y       = (const float*)d_in[1];
    const float* qkv_w   = (const float*)d_in[2];
    const float* proj1_w = (const float*)d_in[3];
    const float* proj1_b = (const float*)d_in[4];
    const float* proj2_w = (const float*)d_in[5];
    const float* proj2_b = (const float*)d_in[6];
    float* out = (float*)d_out;

    float *qkv_p, *red_p;
    __nv_bfloat16 *xhi, *xlo, *wqhi, *wqlo, *w1hi, *w1lo, *w2hi, *w2lo;
    __nv_bfloat16 *aLhi, *aLlo, *aGhi, *aGlo;
    cudaGetSymbolAddress((void**)&qkv_p, g_qkv);
    cudaGetSymbolAddress((void**)&red_p, g_red);
    cudaGetSymbolAddress((void**)&xhi, g_xhi);   cudaGetSymbolAddress((void**)&xlo, g_xlo);
    cudaGetSymbolAddress((void**)&wqhi, g_wqhi); cudaGetSymbolAddress((void**)&wqlo, g_wqlo);
    cudaGetSymbolAddress((void**)&w1hi, g_w1hi); cudaGetSymbolAddress((void**)&w1lo, g_w1lo);
    cudaGetSymbolAddress((void**)&w2hi, g_w2hi); cudaGetSymbolAddress((void**)&w2lo, g_w2lo);
    cudaGetSymbolAddress((void**)&aLhi, g_aLhi); cudaGetSymbolAddress((void**)&aLlo, g_aLlo);
    cudaGetSymbolAddress((void**)&aGhi, g_aGhi); cudaGetSymbolAddress((void**)&aGlo, g_aGlo);

    cudaFuncSetAttribute(gemm_mma<true, false>,
                         cudaFuncAttributeMaxDynamicSharedMemorySize, GEMM_SMEM);
    cudaFuncSetAttribute(gemm_mma<false, true>,
                         cudaFuncAttributeMaxDynamicSharedMemorySize, GEMM_SMEM);

    // 0) split inputs/weights into bf16 hi/lo
    split_kernel<<<(M_ROWS * CH / 4 + 255) / 256, 256>>>(x, xhi, xlo, M_ROWS * CH);
    split_kernel<<<(QKV_N * CH / 4 + 255) / 256, 256>>>(qkv_w, wqhi, wqlo, QKV_N * CH);
    split_kernel<<<(CH * CH / 4 + 255) / 256, 256>>>(proj1_w, w1hi, w1lo, CH * CH);
    split_kernel<<<(CH * CH / 4 + 255) / 256, 256>>>(proj2_w, w2hi, w2lo, CH * CH);

    // 1) qkv = x @ qkv_w^T (delu fused on q,k cols)
    {
        dim3 grid(QKV_N / BNt, M_ROWS / BMt);
        gemm_mma<true, false><<<grid, 256, GEMM_SMEM>>>(
            xhi, xlo, wqhi, wqlo, nullptr, qkv_p, QKV_N, 2 * CH);
    }

    // 2) reductions over N
    zero_red_kernel<<<(3 * BATCH * CH + 255) / 256, 256>>>(red_p);
    {
        dim3 grid(BATCH * NHEAD, NCHUNKS);
        reduce_kernel<<<grid, 256>>>(qkv_p, y, red_p);
    }

    // 3) norm + elementwise attention -> bf16 hi/lo operands
    attn_kernel<<<M_ROWS, 768>>>(qkv_p, red_p, aLhi, aLlo, aGhi, aGlo);

    // 4) output projections (+bias) into d_out
    {
        dim3 grid(CH / BNt, M_ROWS / BMt);
        gemm_mma<false, true><<<grid, 256, GEMM_SMEM>>>(
            aLhi, aLlo, w1hi, w1lo, proj1_b, out, CH, 0);
        gemm_mma<false, true><<<grid, 256, GEMM_SMEM>>>(
            aGhi, aGlo, w2hi, w2lo, proj2_b, out + BNC, CH, 0);
    }
}

// round 6
// speedup vs baseline: 3.6034x; 1.4180x over previous
#include <cuda_runtime.h>
#include <cuda_fp16.h>
#include <cstdint>
#include <math.h>

// ---------------- problem constants ----------------
#define BATCH 4
#define SEQ   4096
#define CH    768
#define NHEAD 12
#define HDIM  64
#define M_ROWS (BATCH * SEQ)          // 16384
#define QKV_N  (3 * CH)               // 2304
#define BNC   (M_ROWS * CH)
#define SCALE 0.125f
#define EPSV  1e-10f
#define KDIM  768
#define ASCALE 4096.0f
#define INV_ASCALE (1.0f / 4096.0f)

// ---------------- scratch (device globals) ----------------
__device__ float g_qkv[M_ROWS * QKV_N];
__device__ __half g_xhi[M_ROWS * CH], g_xlo[M_ROWS * CH];
__device__ __half g_wq[QKV_N * CH];
__device__ __half g_w1[CH * CH], g_w2[CH * CH];
__device__ __half g_aLhi[M_ROWS * CH], g_aLlo[M_ROWS * CH];
__device__ __half g_aGhi[M_ROWS * CH], g_aGlo[M_ROWS * CH];
__device__ float g_red[3 * BATCH * CH];

// ---------------- helpers ----------------
__device__ __forceinline__ float delu_f(float x) {
    return (x >= 0.0f) ? fmaf(10.0f, x, 1.0f) : __expf(10.0f * x);
}

__device__ __forceinline__ uint32_t smem_u32(const void* p) {
    uint32_t a;
    asm("{ .reg .u64 t; cvta.to.shared.u64 t, %1; cvt.u32.u64 %0, t; }" : "=r"(a) : "l"(p));
    return a;
}

__device__ __forceinline__ void cp16(uint32_t s, const void* g) {
    asm volatile("cp.async.cg.shared.global [%0], [%1], 16;" :: "r"(s), "l"(g));
}
#define CP_COMMIT() asm volatile("cp.async.commit_group;" ::: "memory")

__device__ __forceinline__ void ldsm4(uint32_t* r, uint32_t a) {
    asm volatile("ldmatrix.sync.aligned.m8n8.x4.shared.b16 {%0,%1,%2,%3}, [%4];"
                 : "=r"(r[0]), "=r"(r[1]), "=r"(r[2]), "=r"(r[3]) : "r"(a));
}

__device__ __forceinline__ void mma16816(float* c, const uint32_t* a, const uint32_t* b) {
    asm volatile(
        "mma.sync.aligned.m16n8k16.row.col.f32.f16.f16.f32 "
        "{%0,%1,%2,%3},{%4,%5,%6,%7},{%8,%9},{%0,%1,%2,%3};"
        : "+f"(c[0]), "+f"(c[1]), "+f"(c[2]), "+f"(c[3])
        : "r"(a[0]), "r"(a[1]), "r"(a[2]), "r"(a[3]), "r"(b[0]), "r"(b[1]));
}

// ---------------- split-fp16 HMMA GEMM (2 passes) ----------------
// C[M,Nn] = (Ahi + Alo)[M,768] @ B[Nn,768]^T, fp32 accumulate.
// Tile 128x128, BK=64, 256 threads (8 warps, warp tile 64x32), 2-stage cp.async.
#define BMt 128
#define BNt 128
#define BKt 64
#define NKT (KDIM / BKt)             // 12
#define OFF_ALO 16384
#define OFF_B   32768
#define STG 49152                    // 3 tiles x 16KB
#define GEMM_SMEM (2 * STG + 128)

template <bool DELU, bool BIAS>
__global__ void __launch_bounds__(256, 2)
gemm_mma(const __half* __restrict__ Ahi, const __half* __restrict__ Alo,
         const __half* __restrict__ B, const float* __restrict__ bias,
         float* __restrict__ C, int Nn, int delu_limit, float descale)
{
    extern __shared__ char smraw[];
    const uint32_t sbase = (smem_u32(smraw) + 127u) & ~127u;
    const int tid  = threadIdx.x;
    const int lane = tid & 31, wid = tid >> 5;
    const int warp_m = wid >> 2, warp_n = wid & 3;     // 2 x 4 warps
    const int m0 = blockIdx.y * BMt, n0 = blockIdx.x * BNt;

    float acc[4][4][4];
#pragma unroll
    for (int i = 0; i < 4; i++)
#pragma unroll
        for (int j = 0; j < 4; j++)
#pragma unroll
            for (int e = 0; e < 4; e++) acc[i][j][e] = 0.0f;

    auto load_tile = [&](int kt, int s) {
        const uint32_t st = sbase + s * STG;
        const int kb = kt * BKt;
#pragma unroll
        for (int i = tid; i < 1024; i += 256) {
            const int r = i >> 3, cc = i & 7;
            uint32_t off = (uint32_t)(r * 128 + cc * 16);
            off ^= (off >> 3) & 0x70;
            const size_t ga = (size_t)(m0 + r) * KDIM + kb + cc * 8;
            const size_t gb = (size_t)(n0 + r) * KDIM + kb + cc * 8;
            cp16(st + off,           Ahi + ga);
            cp16(st + OFF_ALO + off, Alo + ga);
            cp16(st + OFF_B + off,   B + gb);
        }
        CP_COMMIT();
    };

    load_tile(0, 0);

    const uint32_t arow = (uint32_t)((warp_m * 64 + (lane & 15)) * 128 + (lane >> 4) * 16);
    const uint32_t brow = (uint32_t)((warp_n * 32 + (lane & 15)) * 128 + (lane >> 4) * 16);

    for (int c = 0; c < NKT; c++) {
        const int s = c & 1;
        if (c + 1 < NKT) load_tile(c + 1, s ^ 1);
        if (c + 1 < NKT) asm volatile("cp.async.wait_group 1;" ::: "memory");
        else             asm volatile("cp.async.wait_group 0;" ::: "memory");
        __syncthreads();

        const uint32_t st = sbase + s * STG;
#pragma unroll
        for (int ks = 0; ks < 4; ks++) {
            const uint32_t kofs = ks * 32;
            uint32_t ah[4][4], al[4][4], bh[4][2];
#pragma unroll
            for (int mf = 0; mf < 4; mf++) {
                uint32_t off = arow + mf * 2048 + kofs;
                off ^= (off >> 3) & 0x70;
                ldsm4(ah[mf], st + off);
                ldsm4(al[mf], st + OFF_ALO + off);
            }
#pragma unroll
            for (int g = 0; g < 2; g++) {
                uint32_t off = brow + g * 2048 + kofs;
                off ^= (off >> 3) & 0x70;
                uint32_t q[4];
                ldsm4(q, st + OFF_B + off);
                bh[g * 2][0] = q[0]; bh[g * 2][1] = q[2];
                bh[g * 2 + 1][0] = q[1]; bh[g * 2 + 1][1] = q[3];
            }
#pragma unroll
            for (int mf = 0; mf < 4; mf++)
#pragma unroll
                for (int nf = 0; nf < 4; nf++) {
                    mma16816(acc[mf][nf], ah[mf], bh[nf]);
                    mma16816(acc[mf][nf], al[mf], bh[nf]);
                }
        }
        __syncthreads();
    }

    // ---- epilogue ----
#pragma unroll
    for (int mf = 0; mf < 4; mf++) {
        const int row = m0 + warp_m * 64 + mf * 16 + (lane >> 2);
#pragma unroll
        for (int nf = 0; nf < 4; nf++) {
            const int col = n0 + warp_n * 32 + nf * 8 + (lane & 3) * 2;
            float v0 = acc[mf][nf][0] * descale, v1 = acc[mf][nf][1] * descale;
            float v2 = acc[mf][nf][2] * descale, v3 = acc[mf][nf][3] * descale;
            if (BIAS) {
                const float b0 = bias[col], b1 = bias[col + 1];
                v0 += b0; v1 += b1; v2 += b0; v3 += b1;
            }
            if (DELU && col < delu_limit) {
                v0 = delu_f(v0); v1 = delu_f(v1); v2 = delu_f(v2); v3 = delu_f(v3);
            }
            float2* p0 = reinterpret_cast<float2*>(C + (size_t)row * Nn + col);
            float2* p1 = reinterpret_cast<float2*>(C + (size_t)(row + 8) * Nn + col);
            *p0 = make_float2(v0, v1);
            *p1 = make_float2(v2, v3);
        }
    }
}

// ---------------- f32 -> fp16 hi/lo split ----------------
__global__ void split_kernel(const float* __restrict__ src,
                             __half* __restrict__ hi, __half* __restrict__ lo, int n)
{
    int i = (blockIdx.x * blockDim.x + threadIdx.x) * 4;
    if (i >= n) return;
    float4 v = *reinterpret_cast<const float4*>(src + i);
    __half h0 = __float2half(v.x), h1 = __float2half(v.y);
    __half h2 = __float2half(v.z), h3 = __float2half(v.w);
    __half l0 = __float2half(v.x - __half2float(h0));
    __half l1 = __float2half(v.y - __half2float(h1));
    __half l2 = __float2half(v.z - __half2float(h2));
    __half l3 = __float2half(v.w - __half2float(h3));
    __half2* H = reinterpret_cast<__half2*>(hi + i);
    __half2* L = reinterpret_cast<__half2*>(lo + i);
    H[0] = __halves2half2(h0, h1); H[1] = __halves2half2(h2, h3);
    L[0] = __halves2half2(l0, l1); L[1] = __halves2half2(l2, l3);
}

// ---------------- f32 -> fp16 single (weights) ----------------
__global__ void conv_kernel(const float* __restrict__ src, __half* __restrict__ dst, int n)
{
    int i = (blockIdx.x * blockDim.x + threadIdx.x) * 4;
    if (i >= n) return;
    float4 v = *reinterpret_cast<const float4*>(src + i);
    __half2* D = reinterpret_cast<__half2*>(dst + i);
    D[0] = __halves2half2(__float2half(v.x), __float2half(v.y));
    D[1] = __halves2half2(__float2half(v.z), __float2half(v.w));
}

// ---------------- zero reduction accumulators ----------------
__global__ void zero_red_kernel(float* __restrict__ red) {
    int i = blockIdx.x * blockDim.x + threadIdx.x;
    if (i < 3 * BATCH * CH) red[i] = 0.0f;
}

// ---------------- reductions over N per (b,h,d) ----------------
#define NCHUNKS 8
__global__ void __launch_bounds__(256)
reduce_kernel(const float* __restrict__ qkv, const float* __restrict__ y,
              float* __restrict__ red)
{
    const int bh  = blockIdx.x;
    const int b   = bh / NHEAD;
    const int h   = bh % NHEAD;
    const int tid = threadIdx.x;
    const int d   = tid & 63;
    const int sub = tid >> 6;
    const int nper = SEQ / NCHUNKS;
    const int n0 = blockIdx.y * nper;

    const int colk = CH + h * HDIM + d;
    const int colv = 2 * CH + h * HDIM + d;
    const int coly = h * HDIM + d;

    float akv = 0.f, alkv = 0.f, aks = 0.f;
    for (int n = n0 + sub; n < n0 + nper; n += 4) {
        const long r = (long)b * SEQ + n;
        const float kv_ = qkv[r * QKV_N + colk];
        const float vv  = qkv[r * QKV_N + colv];
        const float lk  = delu_f(y[r * CH + coly]);
        akv  = fmaf(kv_, vv, akv);
        alkv = fmaf(lk,  vv, alkv);
        aks += kv_;
    }

    __shared__ float s[3][256];
    s[0][tid] = akv; s[1][tid] = alkv; s[2][tid] = aks;
    __syncthreads();
    if (sub == 0) {
        const int o = b * CH + h * HDIM + d;
        float r0 = s[0][d] + s[0][64 + d] + s[0][128 + d] + s[0][192 + d];
        float r1 = s[1][d] + s[1][64 + d] + s[1][128 + d] + s[1][192 + d];
        float r2 = s[2][d] + s[2][64 + d] + s[2][128 + d] + s[2][192 + d];
        atomicAdd(&red[o], r0);
        atomicAdd(&red[BATCH * CH + o], r1);
        atomicAdd(&red[2 * BATCH * CH + o], r2);
    }
}

// ---------------- norm + attn elementwise -> scaled fp16 hi/lo ----------------
__global__ void __launch_bounds__(768)
attn_kernel(const float* __restrict__ qkv, const float* __restrict__ red,
            __half* __restrict__ oLh, __half* __restrict__ oLl,
            __half* __restrict__ oGh, __half* __restrict__ oGl)
{
    const int bn = blockIdx.x;
    const int b  = bn >> 12;
    const int c  = threadIdx.x;
    const int h  = c >> 6;

    const float q  = qkv[(long)bn * QKV_N + c];
    const float ks = red[2 * BATCH * CH + b * CH + c] + EPSV;
    float p = q * ks;
#pragma unroll
    for (int off = 16; off; off >>= 1)
        p += __shfl_down_sync(0xffffffffu, p, off);

    __shared__ float ws[24];
    const int warp = c >> 5;
    if ((c & 31) == 0) ws[warp] = p;
    __syncthreads();

    const float norm = ASCALE / (ws[2 * h] + ws[2 * h + 1]);
    const float kvd  = red[b * CH + c] * SCALE;
    const float lkvd = red[BATCH * CH + b * CH + c] * SCALE;

    const float aL = q * kvd  * norm;   // scaled by ASCALE
    const float aG = q * lkvd * norm;
    const size_t idx = (size_t)bn * CH + c;
    __half hL = __float2half(aL);
    __half hG = __float2half(aG);
    oLh[idx] = hL; oLl[idx] = __float2half(aL - __half2float(hL));
    oGh[idx] = hG; oGl[idx] = __float2half(aG - __half2float(hG));
}

// ---------------- launch ----------------
extern "C" void kernel_launch(void* const* d_in, const int* in_sizes, int n_in,
                              void* d_out, int out_size)
{
    const float* x       = (const float*)d_in[0];
    const float* y       = (const float*)d_in[1];
    const float* qkv_w   = (const float*)d_in[2];
    const float* proj1_w = (const float*)d_in[3];
    const float* proj1_b = (const float*)d_in[4];
    const float* proj2_w = (const float*)d_in[5];
    const float* proj2_b = (const float*)d_in[6];
    float* out = (float*)d_out;

    float *qkv_p, *red_p;
    __half *xhi, *xlo, *wq, *w1, *w2, *aLhi, *aLlo, *aGhi, *aGlo;
    cudaGetSymbolAddress((void**)&qkv_p, g_qkv);
    cudaGetSymbolAddress((void**)&red_p, g_red);
    cudaGetSymbolAddress((void**)&xhi, g_xhi);   cudaGetSymbolAddress((void**)&xlo, g_xlo);
    cudaGetSymbolAddress((void**)&wq, g_wq);
    cudaGetSymbolAddress((void**)&w1, g_w1);     cudaGetSymbolAddress((void**)&w2, g_w2);
    cudaGetSymbolAddress((void**)&aLhi, g_aLhi); cudaGetSymbolAddress((void**)&aLlo, g_aLlo);
    cudaGetSymbolAddress((void**)&aGhi, g_aGhi); cudaGetSymbolAddress((void**)&aGlo, g_aGlo);

    cudaFuncSetAttribute(gemm_mma<true, false>,
                         cudaFuncAttributeMaxDynamicSharedMemorySize, GEMM_SMEM);
    cudaFuncSetAttribute(gemm_mma<false, true>,
                         cudaFuncAttributeMaxDynamicSharedMemorySize, GEMM_SMEM);

    // 0) convert: x -> fp16 hi/lo, weights -> fp16
    split_kernel<<<(M_ROWS * CH / 4 + 255) / 256, 256>>>(x, xhi, xlo, M_ROWS * CH);
    conv_kernel<<<(QKV_N * CH / 4 + 255) / 256, 256>>>(qkv_w, wq, QKV_N * CH);
    conv_kernel<<<(CH * CH / 4 + 255) / 256, 256>>>(proj1_w, w1, CH * CH);
    conv_kernel<<<(CH * CH / 4 + 255) / 256, 256>>>(proj2_w, w2, CH * CH);

    // 1) qkv = x @ qkv_w^T (delu fused on q,k cols)
    {
        dim3 grid(QKV_N / BNt, M_ROWS / BMt);
        gemm_mma<true, false><<<grid, 256, GEMM_SMEM>>>(
            xhi, xlo, wq, nullptr, qkv_p, QKV_N, 2 * CH, 1.0f);
    }

    // 2) reductions over N
    zero_red_kernel<<<(3 * BATCH * CH + 255) / 256, 256>>>(red_p);
    {
        dim3 grid(BATCH * NHEAD, NCHUNKS);
        reduce_kernel<<<grid, 256>>>(qkv_p, y, red_p);
    }

    // 3) norm + elementwise attention -> scaled fp16 hi/lo operands
    attn_kernel<<<M_ROWS, 768>>>(qkv_p, red_p, aLhi, aLlo, aGhi, aGlo);

    // 4) output projections (+bias, with 1/ASCALE descale) into d_out
    {
        dim3 grid(CH / BNt, M_ROWS / BMt);
        gemm_mma<false, true><<<grid, 256, GEMM_SMEM>>>(
            aLhi, aLlo, w1, proj1_b, out, CH, 0, INV_ASCALE);
        gemm_mma<false, true><<<grid, 256, GEMM_SMEM>>>(
            aGhi, aGlo, w2, proj2_b, out + BNC, CH, 0, INV_ASCALE);
    }
}

// round 7
// speedup vs baseline: 4.3080x; 1.1955x over previous
#include <cuda_runtime.h>
#include <cuda_fp16.h>
#include <cstdint>
#include <math.h>

// ---------------- problem constants ----------------
#define BATCH 4
#define SEQ   4096
#define CH    768
#define NHEAD 12
#define HDIM  64
#define M_ROWS (BATCH * SEQ)          // 16384
#define QKV_N  (3 * CH)               // 2304
#define BNC   (M_ROWS * CH)
#define SCALE 0.125f
#define EPSV  1e-10f
#define KDIM  768
#define ASCALE 4096.0f
#define INV_ASCALE (1.0f / 4096.0f)

// ---------------- scratch (device globals) ----------------
__device__ float g_qkv[M_ROWS * QKV_N];
__device__ __half g_xhi[M_ROWS * CH], g_xlo[M_ROWS * CH];
__device__ __half g_wq[QKV_N * CH];
__device__ __half g_w1[CH * CH], g_w2[CH * CH];
__device__ __half g_aL[M_ROWS * CH];
__device__ __half g_aG[M_ROWS * CH];
__device__ float g_red[3 * BATCH * CH];

// ---------------- helpers ----------------
__device__ __forceinline__ float delu_f(float x) {
    return (x >= 0.0f) ? fmaf(10.0f, x, 1.0f) : __expf(10.0f * x);
}

__device__ __forceinline__ uint32_t smem_u32(const void* p) {
    uint32_t a;
    asm("{ .reg .u64 t; cvta.to.shared.u64 t, %1; cvt.u32.u64 %0, t; }" : "=r"(a) : "l"(p));
    return a;
}

__device__ __forceinline__ void cp16(uint32_t s, const void* g) {
    asm volatile("cp.async.cg.shared.global [%0], [%1], 16;" :: "r"(s), "l"(g));
}
#define CP_COMMIT() asm volatile("cp.async.commit_group;" ::: "memory")

__device__ __forceinline__ void ldsm4(uint32_t* r, uint32_t a) {
    asm volatile("ldmatrix.sync.aligned.m8n8.x4.shared.b16 {%0,%1,%2,%3}, [%4];"
                 : "=r"(r[0]), "=r"(r[1]), "=r"(r[2]), "=r"(r[3]) : "r"(a));
}

__device__ __forceinline__ void mma16816(float* c, const uint32_t* a, const uint32_t* b) {
    asm volatile(
        "mma.sync.aligned.m16n8k16.row.col.f32.f16.f16.f32 "
        "{%0,%1,%2,%3},{%4,%5,%6,%7},{%8,%9},{%0,%1,%2,%3};"
        : "+f"(c[0]), "+f"(c[1]), "+f"(c[2]), "+f"(c[3])
        : "r"(a[0]), "r"(a[1]), "r"(a[2]), "r"(a[3]), "r"(b[0]), "r"(b[1]));
}

// ---------------- HMMA GEMM ----------------
// C[M,Nn] = A[M,768] @ B[Nn,768]^T, fp32 accumulate.
// SPLIT: A given as fp16 hi/lo pair -> 2 MMA passes. Else single pass.
// Tile 128x128, BK=64, 256 threads (8 warps, warp tile 64x32), 2-stage cp.async.
#define BMt 128
#define BNt 128
#define BKt 64
#define NKT (KDIM / BKt)             // 12
#define TILE_B 16384                 // one 128x64 fp16 tile
#define GEMM_SMEM_SPLIT  (2 * 3 * TILE_B + 128)
#define GEMM_SMEM_SINGLE (2 * 2 * TILE_B + 128)

template <bool SPLIT, bool DELU, bool BIAS>
__global__ void __launch_bounds__(256, 2)
gemm_mma(const __half* __restrict__ Ahi, const __half* __restrict__ Alo,
         const __half* __restrict__ B, const float* __restrict__ bias,
         float* __restrict__ C, int Nn, int delu_limit, float descale)
{
    constexpr int NTILES = SPLIT ? 3 : 2;
    constexpr int STG = NTILES * TILE_B;
    constexpr int OFF_ALO = TILE_B;                    // only if SPLIT
    constexpr int OFF_B = SPLIT ? 2 * TILE_B : TILE_B;

    extern __shared__ char smraw[];
    const uint32_t sbase = (smem_u32(smraw) + 127u) & ~127u;
    const int tid  = threadIdx.x;
    const int lane = tid & 31, wid = tid >> 5;
    const int warp_m = wid >> 2, warp_n = wid & 3;     // 2 x 4 warps
    const int m0 = blockIdx.y * BMt, n0 = blockIdx.x * BNt;

    float acc[4][4][4];
#pragma unroll
    for (int i = 0; i < 4; i++)
#pragma unroll
        for (int j = 0; j < 4; j++)
#pragma unroll
            for (int e = 0; e < 4; e++) acc[i][j][e] = 0.0f;

    auto load_tile = [&](int kt, int s) {
        const uint32_t st = sbase + s * STG;
        const int kb = kt * BKt;
#pragma unroll
        for (int i = tid; i < 1024; i += 256) {
            const int r = i >> 3, cc = i & 7;
            uint32_t off = (uint32_t)(r * 128 + cc * 16);
            off ^= (off >> 3) & 0x70;
            const size_t ga = (size_t)(m0 + r) * KDIM + kb + cc * 8;
            const size_t gb = (size_t)(n0 + r) * KDIM + kb + cc * 8;
            cp16(st + off,         Ahi + ga);
            if (SPLIT) cp16(st + OFF_ALO + off, Alo + ga);
            cp16(st + OFF_B + off, B + gb);
        }
        CP_COMMIT();
    };

    load_tile(0, 0);

    const uint32_t arow = (uint32_t)((warp_m * 64 + (lane & 15)) * 128 + (lane >> 4) * 16);
    const uint32_t brow = (uint32_t)((warp_n * 32 + (lane & 15)) * 128 + (lane >> 4) * 16);

    for (int c = 0; c < NKT; c++) {
        const int s = c & 1;
        if (c + 1 < NKT) load_tile(c + 1, s ^ 1);
        if (c + 1 < NKT) asm volatile("cp.async.wait_group 1;" ::: "memory");
        else             asm volatile("cp.async.wait_group 0;" ::: "memory");
        __syncthreads();

        const uint32_t st = sbase + s * STG;
#pragma unroll
        for (int ks = 0; ks < 4; ks++) {
            const uint32_t kofs = ks * 32;
            uint32_t ah[4][4], al[4][4], bh[4][2];
#pragma unroll
            for (int mf = 0; mf < 4; mf++) {
                uint32_t off = arow + mf * 2048 + kofs;
                off ^= (off >> 3) & 0x70;
                ldsm4(ah[mf], st + off);
                if (SPLIT) ldsm4(al[mf], st + OFF_ALO + off);
            }
#pragma unroll
            for (int g = 0; g < 2; g++) {
                uint32_t off = brow + g * 2048 + kofs;
                off ^= (off >> 3) & 0x70;
                uint32_t q[4];
                ldsm4(q, st + OFF_B + off);
                bh[g * 2][0] = q[0]; bh[g * 2][1] = q[2];
                bh[g * 2 + 1][0] = q[1]; bh[g * 2 + 1][1] = q[3];
            }
#pragma unroll
            for (int mf = 0; mf < 4; mf++)
#pragma unroll
                for (int nf = 0; nf < 4; nf++) {
                    mma16816(acc[mf][nf], ah[mf], bh[nf]);
                    if (SPLIT) mma16816(acc[mf][nf], al[mf], bh[nf]);
                }
        }
        __syncthreads();
    }

    // ---- epilogue ----
#pragma unroll
    for (int mf = 0; mf < 4; mf++) {
        const int row = m0 + warp_m * 64 + mf * 16 + (lane >> 2);
#pragma unroll
        for (int nf = 0; nf < 4; nf++) {
            const int col = n0 + warp_n * 32 + nf * 8 + (lane & 3) * 2;
            float v0 = acc[mf][nf][0] * descale, v1 = acc[mf][nf][1] * descale;
            float v2 = acc[mf][nf][2] * descale, v3 = acc[mf][nf][3] * descale;
            if (BIAS) {
                const float b0 = bias[col], b1 = bias[col + 1];
                v0 += b0; v1 += b1; v2 += b0; v3 += b1;
            }
            if (DELU && col < delu_limit) {
                v0 = delu_f(v0); v1 = delu_f(v1); v2 = delu_f(v2); v3 = delu_f(v3);
            }
            float2* p0 = reinterpret_cast<float2*>(C + (size_t)row * Nn + col);
            float2* p1 = reinterpret_cast<float2*>(C + (size_t)(row + 8) * Nn + col);
            *p0 = make_float2(v0, v1);
            *p1 = make_float2(v2, v3);
        }
    }
}

// ---------------- f32 -> fp16 hi/lo split ----------------
__global__ void split_kernel(const float* __restrict__ src,
                             __half* __restrict__ hi, __half* __restrict__ lo, int n)
{
    int i = (blockIdx.x * blockDim.x + threadIdx.x) * 4;
    if (i >= n) return;
    float4 v = *reinterpret_cast<const float4*>(src + i);
    __half h0 = __float2half(v.x), h1 = __float2half(v.y);
    __half h2 = __float2half(v.z), h3 = __float2half(v.w);
    __half l0 = __float2half(v.x - __half2float(h0));
    __half l1 = __float2half(v.y - __half2float(h1));
    __half l2 = __float2half(v.z - __half2float(h2));
    __half l3 = __float2half(v.w - __half2float(h3));
    __half2* H = reinterpret_cast<__half2*>(hi + i);
    __half2* L = reinterpret_cast<__half2*>(lo + i);
    H[0] = __halves2half2(h0, h1); H[1] = __halves2half2(h2, h3);
    L[0] = __halves2half2(l0, l1); L[1] = __halves2half2(l2, l3);
}

// ---------------- f32 -> fp16 (weights) ----------------
__global__ void conv_kernel(const float* __restrict__ src, __half* __restrict__ dst, int n)
{
    int i = (blockIdx.x * blockDim.x + threadIdx.x) * 4;
    if (i >= n) return;
    float4 v = *reinterpret_cast<const float4*>(src + i);
    __half2* D = reinterpret_cast<__half2*>(dst + i);
    D[0] = __halves2half2(__float2half(v.x), __float2half(v.y));
    D[1] = __halves2half2(__float2half(v.z), __float2half(v.w));
}

// ---------------- zero reduction accumulators ----------------
__global__ void zero_red_kernel(float* __restrict__ red) {
    int i = blockIdx.x * blockDim.x + threadIdx.x;
    if (i < 3 * BATCH * CH) red[i] = 0.0f;
}

// ---------------- reductions over N per (b,h,d) ----------------
#define NCHUNKS 8
__global__ void __launch_bounds__(256)
reduce_kernel(const float* __restrict__ qkv, const float* __restrict__ y,
              float* __restrict__ red)
{
    const int bh  = blockIdx.x;
    const int b   = bh / NHEAD;
    const int h   = bh % NHEAD;
    const int tid = threadIdx.x;
    const int d   = tid & 63;
    const int sub = tid >> 6;
    const int nper = SEQ / NCHUNKS;
    const int n0 = blockIdx.y * nper;

    const int colk = CH + h * HDIM + d;
    const int colv = 2 * CH + h * HDIM + d;
    const int coly = h * HDIM + d;

    float akv = 0.f, alkv = 0.f, aks = 0.f;
    for (int n = n0 + sub; n < n0 + nper; n += 4) {
        const long r = (long)b * SEQ + n;
        const float kv_ = qkv[r * QKV_N + colk];
        const float vv  = qkv[r * QKV_N + colv];
        const float lk  = delu_f(y[r * CH + coly]);
        akv  = fmaf(kv_, vv, akv);
        alkv = fmaf(lk,  vv, alkv);
        aks += kv_;
    }

    __shared__ float s[3][256];
    s[0][tid] = akv; s[1][tid] = alkv; s[2][tid] = aks;
    __syncthreads();
    if (sub == 0) {
        const int o = b * CH + h * HDIM + d;
        float r0 = s[0][d] + s[0][64 + d] + s[0][128 + d] + s[0][192 + d];
        float r1 = s[1][d] + s[1][64 + d] + s[1][128 + d] + s[1][192 + d];
        float r2 = s[2][d] + s[2][64 + d] + s[2][128 + d] + s[2][192 + d];
        atomicAdd(&red[o], r0);
        atomicAdd(&red[BATCH * CH + o], r1);
        atomicAdd(&red[2 * BATCH * CH + o], r2);
    }
}

// ---------------- norm + attn elementwise -> scaled fp16 ----------------
__global__ void __launch_bounds__(768)
attn_kernel(const float* __restrict__ qkv, const float* __restrict__ red,
            __half* __restrict__ oL, __half* __restrict__ oG)
{
    const int bn = blockIdx.x;
    const int b  = bn >> 12;
    const int c  = threadIdx.x;
    const int h  = c >> 6;

    const float q  = qkv[(long)bn * QKV_N + c];
    const float ks = red[2 * BATCH * CH + b * CH + c] + EPSV;
    float p = q * ks;
#pragma unroll
    for (int off = 16; off; off >>= 1)
        p += __shfl_down_sync(0xffffffffu, p, off);

    __shared__ float ws[24];
    const int warp = c >> 5;
    if ((c & 31) == 0) ws[warp] = p;
    __syncthreads();

    const float norm = ASCALE / (ws[2 * h] + ws[2 * h + 1]);
    const float kvd  = red[b * CH + c] * SCALE;
    const float lkvd = red[BATCH * CH + b * CH + c] * SCALE;

    const size_t idx = (size_t)bn * CH + c;
    oL[idx] = __float2half(q * kvd  * norm);   // scaled by ASCALE
    oG[idx] = __float2half(q * lkvd * norm);
}

// ---------------- launch ----------------
extern "C" void kernel_launch(void* const* d_in, const int* in_sizes, int n_in,
                              void* d_out, int out_size)
{
    const float* x       = (const float*)d_in[0];
    const float* y       = (const float*)d_in[1];
    const float* qkv_w   = (const float*)d_in[2];
    const float* proj1_w = (const float*)d_in[3];
    const float* proj1_b = (const float*)d_in[4];
    const float* proj2_w = (const float*)d_in[5];
    const float* proj2_b = (const float*)d_in[6];
    float* out = (float*)d_out;

    float *qkv_p, *red_p;
    __half *xhi, *xlo, *wq, *w1, *w2, *aL, *aG;
    cudaGetSymbolAddress((void**)&qkv_p, g_qkv);
    cudaGetSymbolAddress((void**)&red_p, g_red);
    cudaGetSymbolAddress((void**)&xhi, g_xhi); cudaGetSymbolAddress((void**)&xlo, g_xlo);
    cudaGetSymbolAddress((void**)&wq, g_wq);
    cudaGetSymbolAddress((void**)&w1, g_w1);   cudaGetSymbolAddress((void**)&w2, g_w2);
    cudaGetSymbolAddress((void**)&aL, g_aL);   cudaGetSymbolAddress((void**)&aG, g_aG);

    cudaFuncSetAttribute(gemm_mma<true, true, false>,
                         cudaFuncAttributeMaxDynamicSharedMemorySize, GEMM_SMEM_SPLIT);
    cudaFuncSetAttribute(gemm_mma<false, false, true>,
                         cudaFuncAttributeMaxDynamicSharedMemorySize, GEMM_SMEM_SINGLE);

    // 0) convert: x -> fp16 hi/lo, weights -> fp16
    split_kernel<<<(M_ROWS * CH / 4 + 255) / 256, 256>>>(x, xhi, xlo, M_ROWS * CH);
    conv_kernel<<<(QKV_N * CH / 4 + 255) / 256, 256>>>(qkv_w, wq, QKV_N * CH);
    conv_kernel<<<(CH * CH / 4 + 255) / 256, 256>>>(proj1_w, w1, CH * CH);
    conv_kernel<<<(CH * CH / 4 + 255) / 256, 256>>>(proj2_w, w2, CH * CH);

    // 1) qkv = x @ qkv_w^T (delu fused on q,k cols) — split A, 2 passes
    {
        dim3 grid(QKV_N / BNt, M_ROWS / BMt);
        gemm_mma<true, true, false><<<grid, 256, GEMM_SMEM_SPLIT>>>(
            xhi, xlo, wq, nullptr, qkv_p, QKV_N, 2 * CH, 1.0f);
    }

    // 2) reductions over N
    zero_red_kernel<<<(3 * BATCH * CH + 255) / 256, 256>>>(red_p);
    {
        dim3 grid(BATCH * NHEAD, NCHUNKS);
        reduce_kernel<<<grid, 256>>>(qkv_p, y, red_p);
    }

    // 3) norm + elementwise attention -> scaled fp16 operands
    attn_kernel<<<M_ROWS, 768>>>(qkv_p, red_p, aL, aG);

    // 4) output projections (+bias, 1/ASCALE descale) — single-pass A
    {
        dim3 grid(CH / BNt, M_ROWS / BMt);
        gemm_mma<false, false, true><<<grid, 256, GEMM_SMEM_SINGLE>>>(
            aL, nullptr, w1, proj1_b, out, CH, 0, INV_ASCALE);
        gemm_mma<false, false, true><<<grid, 256, GEMM_SMEM_SINGLE>>>(
            aG, nullptr, w2, proj2_b, out + BNC, CH, 0, INV_ASCALE);
    }
}

// round 8
// speedup vs baseline: 5.6932x; 1.3215x over previous
#include <cuda_runtime.h>
#include <cuda_fp16.h>
#include <cstdint>
#include <math.h>

// ---------------- problem constants ----------------
#define BATCH 4
#define SEQ   4096
#define CH    768
#define NHEAD 12
#define HDIM  64
#define M_ROWS (BATCH * SEQ)          // 16384
#define QKV_N  (3 * CH)               // 2304
#define BNC   (M_ROWS * CH)
#define SCALE 0.125f
#define EPSV  1e-10f
#define KDIM  768
#define ASCALE 4096.0f
#define INV_ASCALE (1.0f / 4096.0f)

// ---------------- scratch (device globals) ----------------
__device__ float g_qkv[M_ROWS * QKV_N];
__device__ __half g_x16[M_ROWS * CH];
__device__ __half g_wq[QKV_N * CH];
__device__ __half g_w1[CH * CH], g_w2[CH * CH];
__device__ __half g_aL[M_ROWS * CH];
__device__ __half g_aG[M_ROWS * CH];
__device__ float g_red[3 * BATCH * CH];

// ---------------- helpers ----------------
__device__ __forceinline__ float delu_f(float x) {
    return (x >= 0.0f) ? fmaf(10.0f, x, 1.0f) : __expf(10.0f * x);
}

__device__ __forceinline__ uint32_t smem_u32(const void* p) {
    uint32_t a;
    asm("{ .reg .u64 t; cvta.to.shared.u64 t, %1; cvt.u32.u64 %0, t; }" : "=r"(a) : "l"(p));
    return a;
}

__device__ __forceinline__ void cp16(uint32_t s, const void* g) {
    asm volatile("cp.async.cg.shared.global [%0], [%1], 16;" :: "r"(s), "l"(g));
}
#define CP_COMMIT() asm volatile("cp.async.commit_group;" ::: "memory")

__device__ __forceinline__ void ldsm4(uint32_t* r, uint32_t a) {
    asm volatile("ldmatrix.sync.aligned.m8n8.x4.shared.b16 {%0,%1,%2,%3}, [%4];"
                 : "=r"(r[0]), "=r"(r[1]), "=r"(r[2]), "=r"(r[3]) : "r"(a));
}

__device__ __forceinline__ void mma16816(float* c, const uint32_t* a, const uint32_t* b) {
    asm volatile(
        "mma.sync.aligned.m16n8k16.row.col.f32.f16.f16.f32 "
        "{%0,%1,%2,%3},{%4,%5,%6,%7},{%8,%9},{%0,%1,%2,%3};"
        : "+f"(c[0]), "+f"(c[1]), "+f"(c[2]), "+f"(c[3])
        : "r"(a[0]), "r"(a[1]), "r"(a[2]), "r"(a[3]), "r"(b[0]), "r"(b[1]));
}

// ---------------- single-pass HMMA GEMM ----------------
// C[M,Nn] = A[M,768] @ B[Nn,768]^T, fp32 accumulate.
// Tile 128x128, BK=64, 256 threads (8 warps, warp tile 64x32), 2-stage cp.async.
#define BMt 128
#define BNt 128
#define BKt 64
#define NKT (KDIM / BKt)             // 12
#define TILE_B 16384                 // one 128x64 fp16 tile
#define OFF_B TILE_B
#define STG (2 * TILE_B)
#define GEMM_SMEM (2 * STG + 128)

template <bool DELU, bool BIAS>
__global__ void __launch_bounds__(256, 2)
gemm_mma(const __half* __restrict__ A, const __half* __restrict__ B,
         const float* __restrict__ bias, float* __restrict__ C,
         int Nn, int delu_limit, float descale)
{
    extern __shared__ char smraw[];
    const uint32_t sbase = (smem_u32(smraw) + 127u) & ~127u;
    const int tid  = threadIdx.x;
    const int lane = tid & 31, wid = tid >> 5;
    const int warp_m = wid >> 2, warp_n = wid & 3;     // 2 x 4 warps
    const int m0 = blockIdx.y * BMt, n0 = blockIdx.x * BNt;

    float acc[4][4][4];
#pragma unroll
    for (int i = 0; i < 4; i++)
#pragma unroll
        for (int j = 0; j < 4; j++)
#pragma unroll
            for (int e = 0; e < 4; e++) acc[i][j][e] = 0.0f;

    auto load_tile = [&](int kt, int s) {
        const uint32_t st = sbase + s * STG;
        const int kb = kt * BKt;
#pragma unroll
        for (int i = tid; i < 1024; i += 256) {
            const int r = i >> 3, cc = i & 7;
            uint32_t off = (uint32_t)(r * 128 + cc * 16);
            off ^= (off >> 3) & 0x70;
            const size_t ga = (size_t)(m0 + r) * KDIM + kb + cc * 8;
            const size_t gb = (size_t)(n0 + r) * KDIM + kb + cc * 8;
            cp16(st + off,         A + ga);
            cp16(st + OFF_B + off, B + gb);
        }
        CP_COMMIT();
    };

    load_tile(0, 0);

    const uint32_t arow = (uint32_t)((warp_m * 64 + (lane & 15)) * 128 + (lane >> 4) * 16);
    const uint32_t brow = (uint32_t)((warp_n * 32 + (lane & 15)) * 128 + (lane >> 4) * 16);

    for (int c = 0; c < NKT; c++) {
        const int s = c & 1;
        if (c + 1 < NKT) load_tile(c + 1, s ^ 1);
        if (c + 1 < NKT) asm volatile("cp.async.wait_group 1;" ::: "memory");
        else             asm volatile("cp.async.wait_group 0;" ::: "memory");
        __syncthreads();

        const uint32_t st = sbase + s * STG;
#pragma unroll
        for (int ks = 0; ks < 4; ks++) {
            const uint32_t kofs = ks * 32;
            uint32_t ah[4][4], bh[4][2];
#pragma unroll
            for (int mf = 0; mf < 4; mf++) {
                uint32_t off = arow + mf * 2048 + kofs;
                off ^= (off >> 3) & 0x70;
                ldsm4(ah[mf], st + off);
            }
#pragma unroll
            for (int g = 0; g < 2; g++) {
                uint32_t off = brow + g * 2048 + kofs;
                off ^= (off >> 3) & 0x70;
                uint32_t q[4];
                ldsm4(q, st + OFF_B + off);
                bh[g * 2][0] = q[0]; bh[g * 2][1] = q[2];
                bh[g * 2 + 1][0] = q[1]; bh[g * 2 + 1][1] = q[3];
            }
#pragma unroll
            for (int mf = 0; mf < 4; mf++)
#pragma unroll
                for (int nf = 0; nf < 4; nf++)
                    mma16816(acc[mf][nf], ah[mf], bh[nf]);
        }
        __syncthreads();
    }

    // ---- epilogue ----
#pragma unroll
    for (int mf = 0; mf < 4; mf++) {
        const int row = m0 + warp_m * 64 + mf * 16 + (lane >> 2);
#pragma unroll
        for (int nf = 0; nf < 4; nf++) {
            const int col = n0 + warp_n * 32 + nf * 8 + (lane & 3) * 2;
            float v0 = acc[mf][nf][0] * descale, v1 = acc[mf][nf][1] * descale;
            float v2 = acc[mf][nf][2] * descale, v3 = acc[mf][nf][3] * descale;
            if (BIAS) {
                const float b0 = bias[col], b1 = bias[col + 1];
                v0 += b0; v1 += b1; v2 += b0; v3 += b1;
            }
            if (DELU && col < delu_limit) {
                v0 = delu_f(v0); v1 = delu_f(v1); v2 = delu_f(v2); v3 = delu_f(v3);
            }
            float2* p0 = reinterpret_cast<float2*>(C + (size_t)row * Nn + col);
            float2* p1 = reinterpret_cast<float2*>(C + (size_t)(row + 8) * Nn + col);
            *p0 = make_float2(v0, v1);
            *p1 = make_float2(v2, v3);
        }
    }
}

// ---------------- f32 -> fp16 convert ----------------
__global__ void conv_kernel(const float* __restrict__ src, __half* __restrict__ dst, int n)
{
    int i = (blockIdx.x * blockDim.x + threadIdx.x) * 4;
    if (i >= n) return;
    float4 v = *reinterpret_cast<const float4*>(src + i);
    __half2* D = reinterpret_cast<__half2*>(dst + i);
    D[0] = __halves2half2(__float2half(v.x), __float2half(v.y));
    D[1] = __halves2half2(__float2half(v.z), __float2half(v.w));
}

// ---------------- zero reduction accumulators ----------------
__global__ void zero_red_kernel(float* __restrict__ red) {
    int i = blockIdx.x * blockDim.x + threadIdx.x;
    if (i < 3 * BATCH * CH) red[i] = 0.0f;
}

// ---------------- reductions over N per (b,h,d) ----------------
#define NCHUNKS 8
__global__ void __launch_bounds__(256)
reduce_kernel(const float* __restrict__ qkv, const float* __restrict__ y,
              float* __restrict__ red)
{
    const int bh  = blockIdx.x;
    const int b   = bh / NHEAD;
    const int h   = bh % NHEAD;
    const int tid = threadIdx.x;
    const int d   = tid & 63;
    const int sub = tid >> 6;
    const int nper = SEQ / NCHUNKS;
    const int n0 = blockIdx.y * nper;

    const int colk = CH + h * HDIM + d;
    const int colv = 2 * CH + h * HDIM + d;
    const int coly = h * HDIM + d;

    float akv = 0.f, alkv = 0.f, aks = 0.f;
    for (int n = n0 + sub; n < n0 + nper; n += 4) {
        const long r = (long)b * SEQ + n;
        const float kv_ = qkv[r * QKV_N + colk];
        const float vv  = qkv[r * QKV_N + colv];
        const float lk  = delu_f(y[r * CH + coly]);
        akv  = fmaf(kv_, vv, akv);
        alkv = fmaf(lk,  vv, alkv);
        aks += kv_;
    }

    __shared__ float s[3][256];
    s[0][tid] = akv; s[1][tid] = alkv; s[2][tid] = aks;
    __syncthreads();
    if (sub == 0) {
        const int o = b * CH + h * HDIM + d;
        float r0 = s[0][d] + s[0][64 + d] + s[0][128 + d] + s[0][192 + d];
        float r1 = s[1][d] + s[1][64 + d] + s[1][128 + d] + s[1][192 + d];
        float r2 = s[2][d] + s[2][64 + d] + s[2][128 + d] + s[2][192 + d];
        atomicAdd(&red[o], r0);
        atomicAdd(&red[BATCH * CH + o], r1);
        atomicAdd(&red[2 * BATCH * CH + o], r2);
    }
}

// ---------------- norm + attn elementwise -> scaled fp16 ----------------
__global__ void __launch_bounds__(768)
attn_kernel(const float* __restrict__ qkv, const float* __restrict__ red,
            __half* __restrict__ oL, __half* __restrict__ oG)
{
    const int bn = blockIdx.x;
    const int b  = bn >> 12;
    const int c  = threadIdx.x;
    const int h  = c >> 6;

    const float q  = qkv[(long)bn * QKV_N + c];
    const float ks = red[2 * BATCH * CH + b * CH + c] + EPSV;
    float p = q * ks;
#pragma unroll
    for (int off = 16; off; off >>= 1)
        p += __shfl_down_sync(0xffffffffu, p, off);

    __shared__ float ws[24];
    const int warp = c >> 5;
    if ((c & 31) == 0) ws[warp] = p;
    __syncthreads();

    const float norm = ASCALE / (ws[2 * h] + ws[2 * h + 1]);
    const float kvd  = red[b * CH + c] * SCALE;
    const float lkvd = red[BATCH * CH + b * CH + c] * SCALE;

    const size_t idx = (size_t)bn * CH + c;
    oL[idx] = __float2half(q * kvd  * norm);   // scaled by ASCALE
    oG[idx] = __float2half(q * lkvd * norm);
}

// ---------------- launch ----------------
extern "C" void kernel_launch(void* const* d_in, const int* in_sizes, int n_in,
                              void* d_out, int out_size)
{
    const float* x       = (const float*)d_in[0];
    const float* y       = (const float*)d_in[1];
    const float* qkv_w   = (const float*)d_in[2];
    const float* proj1_w = (const float*)d_in[3];
    const float* proj1_b = (const float*)d_in[4];
    const float* proj2_w = (const float*)d_in[5];
    const float* proj2_b = (const float*)d_in[6];
    float* out = (float*)d_out;

    float *qkv_p, *red_p;
    __half *x16, *wq, *w1, *w2, *aL, *aG;
    cudaGetSymbolAddress((void**)&qkv_p, g_qkv);
    cudaGetSymbolAddress((void**)&red_p, g_red);
    cudaGetSymbolAddress((void**)&x16, g_x16);
    cudaGetSymbolAddress((void**)&wq, g_wq);
    cudaGetSymbolAddress((void**)&w1, g_w1);   cudaGetSymbolAddress((void**)&w2, g_w2);
    cudaGetSymbolAddress((void**)&aL, g_aL);   cudaGetSymbolAddress((void**)&aG, g_aG);

    cudaFuncSetAttribute(gemm_mma<true, false>,
                         cudaFuncAttributeMaxDynamicSharedMemorySize, GEMM_SMEM);
    cudaFuncSetAttribute(gemm_mma<false, true>,
                         cudaFuncAttributeMaxDynamicSharedMemorySize, GEMM_SMEM);

    // 0) convert x and weights to fp16
    conv_kernel<<<(M_ROWS * CH / 4 + 255) / 256, 256>>>(x, x16, M_ROWS * CH);
    conv_kernel<<<(QKV_N * CH / 4 + 255) / 256, 256>>>(qkv_w, wq, QKV_N * CH);
    conv_kernel<<<(CH * CH / 4 + 255) / 256, 256>>>(proj1_w, w1, CH * CH);
    conv_kernel<<<(CH * CH / 4 + 255) / 256, 256>>>(proj2_w, w2, CH * CH);

    // 1) qkv = x @ qkv_w^T (delu fused on q,k cols) — single pass
    {
        dim3 grid(QKV_N / BNt, M_ROWS / BMt);
        gemm_mma<true, false><<<grid, 256, GEMM_SMEM>>>(
            x16, wq, nullptr, qkv_p, QKV_N, 2 * CH, 1.0f);
    }

    // 2) reductions over N
    zero_red_kernel<<<(3 * BATCH * CH + 255) / 256, 256>>>(red_p);
    {
        dim3 grid(BATCH * NHEAD, NCHUNKS);
        reduce_kernel<<<grid, 256>>>(qkv_p, y, red_p);
    }

    // 3) norm + elementwise attention -> scaled fp16 operands
    attn_kernel<<<M_ROWS, 768>>>(qkv_p, red_p, aL, aG);

    // 4) output projections (+bias, 1/ASCALE descale)
    {
        dim3 grid(CH / BNt, M_ROWS / BMt);
        gemm_mma<false, true><<<grid, 256, GEMM_SMEM>>>(
            aL, w1, proj1_b, out, CH, 0, INV_ASCALE);
        gemm_mma<false, true><<<grid, 256, GEMM_SMEM>>>(
            aG, w2, proj2_b, out + BNC, CH, 0, INV_ASCALE);
    }
}

// round 9
// speedup vs baseline: 6.7392x; 1.1837x over previous
#include <cuda_runtime.h>
#include <cuda_fp16.h>
#include <cstdint>
#include <math.h>

// ---------------- problem constants ----------------
#define BATCH 4
#define SEQ   4096
#define CH    768
#define NHEAD 12
#define HDIM  64
#define M_ROWS (BATCH * SEQ)          // 16384
#define QKV_N  (3 * CH)               // 2304
#define BNC   (M_ROWS * CH)
#define SCALE 0.125f
#define EPSV  1e-10f
#define KDIM  768
#define ASCALE 4096.0f
#define INV_ASCALE (1.0f / 4096.0f)

// ---------------- scratch (device globals) ----------------
__device__ float g_qkv[M_ROWS * QKV_N];
__device__ __half g_x16[M_ROWS * CH];
__device__ __half g_wq[QKV_N * CH];
__device__ __half g_w1[CH * CH], g_w2[CH * CH];
__device__ __half g_aL[M_ROWS * CH];
__device__ __half g_aG[M_ROWS * CH];
__device__ float g_red[3 * BATCH * CH];

// ---------------- helpers ----------------
__device__ __forceinline__ float delu_f(float x) {
    return (x >= 0.0f) ? fmaf(10.0f, x, 1.0f) : __expf(10.0f * x);
}

__device__ __forceinline__ uint32_t smem_u32(const void* p) {
    uint32_t a;
    asm("{ .reg .u64 t; cvta.to.shared.u64 t, %1; cvt.u32.u64 %0, t; }" : "=r"(a) : "l"(p));
    return a;
}

__device__ __forceinline__ void cp16(uint32_t s, const void* g) {
    asm volatile("cp.async.cg.shared.global [%0], [%1], 16;" :: "r"(s), "l"(g));
}
#define CP_COMMIT() asm volatile("cp.async.commit_group;" ::: "memory")

__device__ __forceinline__ void ldsm4(uint32_t* r, uint32_t a) {
    asm volatile("ldmatrix.sync.aligned.m8n8.x4.shared.b16 {%0,%1,%2,%3}, [%4];"
                 : "=r"(r[0]), "=r"(r[1]), "=r"(r[2]), "=r"(r[3]) : "r"(a));
}

__device__ __forceinline__ void mma16816(float* c, const uint32_t* a, const uint32_t* b) {
    asm volatile(
        "mma.sync.aligned.m16n8k16.row.col.f32.f16.f16.f32 "
        "{%0,%1,%2,%3},{%4,%5,%6,%7},{%8,%9},{%0,%1,%2,%3};"
        : "+f"(c[0]), "+f"(c[1]), "+f"(c[2]), "+f"(c[3])
        : "r"(a[0]), "r"(a[1]), "r"(a[2]), "r"(a[3]), "r"(b[0]), "r"(b[1]));
}

// ---------------- single-pass HMMA GEMM, 3-stage pipeline ----------------
// C[M,Nn] = A[M,768] @ B[Nn,768]^T, fp32 accumulate.
// Tile 128x128, BK=64, 256 threads (8 warps, warp tile 64x32).
#define BMt 128
#define BNt 128
#define BKt 64
#define NKT (KDIM / BKt)             // 12
#define TILE_B 16384                 // one 128x64 fp16 tile
#define OFF_B TILE_B
#define STG (2 * TILE_B)             // 32 KB per stage
#define NSTG 3
#define GEMM_SMEM (NSTG * STG + 1024)

template <bool DELU, bool BIAS, bool ZSEL>
__global__ void __launch_bounds__(256, 2)
gemm_mma(const __half* __restrict__ A, const __half* __restrict__ B,
         const float* __restrict__ bias, float* __restrict__ C,
         const __half* __restrict__ A2, const __half* __restrict__ B2,
         const float* __restrict__ bias2, float* __restrict__ C2,
         int Nn, int delu_limit, float descale)
{
    if (ZSEL && blockIdx.z) { A = A2; B = B2; bias = bias2; C = C2; }

    extern __shared__ char smraw[];
    const uint32_t sbase = (smem_u32(smraw) + 1023u) & ~1023u;
    const int tid  = threadIdx.x;
    const int lane = tid & 31, wid = tid >> 5;
    const int warp_m = wid >> 2, warp_n = wid & 3;     // 2 x 4 warps
    const int m0 = blockIdx.y * BMt, n0 = blockIdx.x * BNt;

    float acc[4][4][4];
#pragma unroll
    for (int i = 0; i < 4; i++)
#pragma unroll
        for (int j = 0; j < 4; j++)
#pragma unroll
            for (int e = 0; e < 4; e++) acc[i][j][e] = 0.0f;

    auto load_tile = [&](int kt, int s) {
        const uint32_t st = sbase + s * STG;
        const int kb = kt * BKt;
#pragma unroll
        for (int i = tid; i < 1024; i += 256) {
            const int r = i >> 3, cc = i & 7;
            uint32_t off = (uint32_t)(r * 128 + cc * 16);
            off ^= (off >> 3) & 0x70;
            const size_t ga = (size_t)(m0 + r) * KDIM + kb + cc * 8;
            const size_t gb = (size_t)(n0 + r) * KDIM + kb + cc * 8;
            cp16(st + off,         A + ga);
            cp16(st + OFF_B + off, B + gb);
        }
        CP_COMMIT();
    };

    load_tile(0, 0);
    load_tile(1, 1);

    const uint32_t arow = (uint32_t)((warp_m * 64 + (lane & 15)) * 128 + (lane >> 4) * 16);
    const uint32_t brow = (uint32_t)((warp_n * 32 + (lane & 15)) * 128 + (lane >> 4) * 16);

    for (int c = 0; c < NKT; c++) {
        const int s = c % NSTG;
        if (c == NKT - 1) asm volatile("cp.async.wait_group 0;" ::: "memory");
        else              asm volatile("cp.async.wait_group 1;" ::: "memory");
        __syncthreads();   // stage s ready; all warps done computing stage (c-1)%NSTG

        if (c + 2 < NKT) load_tile(c + 2, (c + 2) % NSTG);

        const uint32_t st = sbase + s * STG;
#pragma unroll
        for (int ks = 0; ks < 4; ks++) {
            const uint32_t kofs = ks * 32;
            uint32_t ah[4][4], bh[4][2];
#pragma unroll
            for (int mf = 0; mf < 4; mf++) {
                uint32_t off = arow + mf * 2048 + kofs;
                off ^= (off >> 3) & 0x70;
                ldsm4(ah[mf], st + off);
            }
#pragma unroll
            for (int g = 0; g < 2; g++) {
                uint32_t off = brow + g * 2048 + kofs;
                off ^= (off >> 3) & 0x70;
                uint32_t q[4];
                ldsm4(q, st + OFF_B + off);
                bh[g * 2][0] = q[0]; bh[g * 2][1] = q[2];
                bh[g * 2 + 1][0] = q[1]; bh[g * 2 + 1][1] = q[3];
            }
#pragma unroll
            for (int mf = 0; mf < 4; mf++)
#pragma unroll
                for (int nf = 0; nf < 4; nf++)
                    mma16816(acc[mf][nf], ah[mf], bh[nf]);
        }
    }

    // ---- epilogue ----
#pragma unroll
    for (int mf = 0; mf < 4; mf++) {
        const int row = m0 + warp_m * 64 + mf * 16 + (lane >> 2);
#pragma unroll
        for (int nf = 0; nf < 4; nf++) {
            const int col = n0 + warp_n * 32 + nf * 8 + (lane & 3) * 2;
            float v0 = acc[mf][nf][0] * descale, v1 = acc[mf][nf][1] * descale;
            float v2 = acc[mf][nf][2] * descale, v3 = acc[mf][nf][3] * descale;
            if (BIAS) {
                const float b0 = bias[col], b1 = bias[col + 1];
                v0 += b0; v1 += b1; v2 += b0; v3 += b1;
            }
            if (DELU && col < delu_limit) {
                v0 = delu_f(v0); v1 = delu_f(v1); v2 = delu_f(v2); v3 = delu_f(v3);
            }
            float2* p0 = reinterpret_cast<float2*>(C + (size_t)row * Nn + col);
            float2* p1 = reinterpret_cast<float2*>(C + (size_t)(row + 8) * Nn + col);
            *p0 = make_float2(v0, v1);
            *p1 = make_float2(v2, v3);
        }
    }
}

// ---------------- f32 -> fp16 convert ----------------
__global__ void conv_kernel(const float* __restrict__ src, __half* __restrict__ dst, int n)
{
    int i = (blockIdx.x * blockDim.x + threadIdx.x) * 4;
    if (i >= n) return;
    float4 v = *reinterpret_cast<const float4*>(src + i);
    __half2* D = reinterpret_cast<__half2*>(dst + i);
    D[0] = __halves2half2(__float2half(v.x), __float2half(v.y));
    D[1] = __halves2half2(__float2half(v.z), __float2half(v.w));
}

// ---------------- zero reduction accumulators ----------------
__global__ void zero_red_kernel(float* __restrict__ red) {
    int i = blockIdx.x * blockDim.x + threadIdx.x;
    if (i < 3 * BATCH * CH) red[i] = 0.0f;
}

// ---------------- reductions over N per (b,h,d), float4 ----------------
#define NCHUNKS 8
__global__ void __launch_bounds__(256)
reduce_kernel(const float* __restrict__ qkv, const float* __restrict__ y,
              float* __restrict__ red)
{
    const int bh  = blockIdx.x;            // 0..47
    const int b   = bh / NHEAD;
    const int h   = bh % NHEAD;
    const int tid = threadIdx.x;
    const int p   = tid & 15;              // which d4 group (d = p*4..p*4+3)
    const int sub = tid >> 4;              // 0..15
    const int nper = SEQ / NCHUNKS;        // 512
    const int n0 = blockIdx.y * nper;

    const int colk = CH + h * HDIM + p * 4;
    const int colv = 2 * CH + h * HDIM + p * 4;
    const int coly = h * HDIM + p * 4;

    float4 akv = make_float4(0.f, 0.f, 0.f, 0.f);
    float4 alkv = make_float4(0.f, 0.f, 0.f, 0.f);
    float4 aks = make_float4(0.f, 0.f, 0.f, 0.f);

    for (int n = n0 + sub; n < n0 + nper; n += 16) {
        const size_t r = (size_t)b * SEQ + n;
        const float4 kv = *reinterpret_cast<const float4*>(qkv + r * QKV_N + colk);
        const float4 vv = *reinterpret_cast<const float4*>(qkv + r * QKV_N + colv);
        const float4 yv = *reinterpret_cast<const float4*>(y + r * CH + coly);
        akv.x = fmaf(kv.x, vv.x, akv.x); akv.y = fmaf(kv.y, vv.y, akv.y);
        akv.z = fmaf(kv.z, vv.z, akv.z); akv.w = fmaf(kv.w, vv.w, akv.w);
        alkv.x = fmaf(delu_f(yv.x), vv.x, alkv.x);
        alkv.y = fmaf(delu_f(yv.y), vv.y, alkv.y);
        alkv.z = fmaf(delu_f(yv.z), vv.z, alkv.z);
        alkv.w = fmaf(delu_f(yv.w), vv.w, alkv.w);
        aks.x += kv.x; aks.y += kv.y; aks.z += kv.z; aks.w += kv.w;
    }

    __shared__ float s[3][16][64];         // [which][sub][d]
    const int d0 = p * 4;
    *reinterpret_cast<float4*>(&s[0][sub][d0]) = akv;
    *reinterpret_cast<float4*>(&s[1][sub][d0]) = alkv;
    *reinterpret_cast<float4*>(&s[2][sub][d0]) = aks;
    __syncthreads();

    if (tid < 64) {
        const int d = tid;
        float r0 = 0.f, r1 = 0.f, r2 = 0.f;
#pragma unroll
        for (int ss = 0; ss < 16; ss++) {
            r0 += s[0][ss][d]; r1 += s[1][ss][d]; r2 += s[2][ss][d];
        }
        const int o = b * CH + h * HDIM + d;
        atomicAdd(&red[o], r0);
        atomicAdd(&red[BATCH * CH + o], r1);
        atomicAdd(&red[2 * BATCH * CH + o], r2);
    }
}

// ---------------- norm + attn: 192 thr/row, float4, no smem ----------------
__global__ void __launch_bounds__(192)
attn_kernel(const float* __restrict__ qkv, const float* __restrict__ red,
            __half* __restrict__ oL, __half* __restrict__ oG)
{
    const int bn = blockIdx.x;             // 0..16383
    const int b  = bn >> 12;
    const int t  = threadIdx.x;            // 0..191
    const int h  = t >> 4;                 // 0..11
    const int p  = t & 15;
    const int c0 = h * HDIM + p * 4;

    const float4 q = *reinterpret_cast<const float4*>(qkv + (size_t)bn * QKV_N + c0);
    const float4 ks = *reinterpret_cast<const float4*>(red + 2 * BATCH * CH + b * CH + c0);

    float pp = q.x * (ks.x + EPSV) + q.y * (ks.y + EPSV)
             + q.z * (ks.z + EPSV) + q.w * (ks.w + EPSV);
#pragma unroll
    for (int off = 8; off; off >>= 1)
        pp += __shfl_xor_sync(0xffffffffu, pp, off, 16);

    const float norm = ASCALE / pp;
    const float4 kvd  = *reinterpret_cast<const float4*>(red + b * CH + c0);
    const float4 lkvd = *reinterpret_cast<const float4*>(red + BATCH * CH + b * CH + c0);

    const size_t idx = (size_t)bn * CH + c0;
    __half2* L = reinterpret_cast<__half2*>(oL + idx);
    __half2* G = reinterpret_cast<__half2*>(oG + idx);
    const float sn = SCALE * norm;
    L[0] = __halves2half2(__float2half(q.x * kvd.x * sn),  __float2half(q.y * kvd.y * sn));
    L[1] = __halves2half2(__float2half(q.z * kvd.z * sn),  __float2half(q.w * kvd.w * sn));
    G[0] = __halves2half2(__float2half(q.x * lkvd.x * sn), __float2half(q.y * lkvd.y * sn));
    G[1] = __halves2half2(__float2half(q.z * lkvd.z * sn), __float2half(q.w * lkvd.w * sn));
}

// ---------------- launch ----------------
extern "C" void kernel_launch(void* const* d_in, const int* in_sizes, int n_in,
                              void* d_out, int out_size)
{
    const float* x       = (const float*)d_in[0];
    const float* y       = (const float*)d_in[1];
    const float* qkv_w   = (const float*)d_in[2];
    const float* proj1_w = (const float*)d_in[3];
    const float* proj1_b = (const float*)d_in[4];
    const float* proj2_w = (const float*)d_in[5];
    const float* proj2_b = (const float*)d_in[6];
    float* out = (float*)d_out;

    float *qkv_p, *red_p;
    __half *x16, *wq, *w1, *w2, *aL, *aG;
    cudaGetSymbolAddress((void**)&qkv_p, g_qkv);
    cudaGetSymbolAddress((void**)&red_p, g_red);
    cudaGetSymbolAddress((void**)&x16, g_x16);
    cudaGetSymbolAddress((void**)&wq, g_wq);
    cudaGetSymbolAddress((void**)&w1, g_w1);   cudaGetSymbolAddress((void**)&w2, g_w2);
    cudaGetSymbolAddress((void**)&aL, g_aL);   cudaGetSymbolAddress((void**)&aG, g_aG);

    cudaFuncSetAttribute(gemm_mma<true, false, false>,
                         cudaFuncAttributeMaxDynamicSharedMemorySize, GEMM_SMEM);
    cudaFuncSetAttribute(gemm_mma<false, true, true>,
                         cudaFuncAttributeMaxDynamicSharedMemorySize, GEMM_SMEM);

    // 0) convert x and weights to fp16
    conv_kernel<<<(M_ROWS * CH / 4 + 255) / 256, 256>>>(x, x16, M_ROWS * CH);
    conv_kernel<<<(QKV_N * CH / 4 + 255) / 256, 256>>>(qkv_w, wq, QKV_N * CH);
    conv_kernel<<<(CH * CH / 4 + 255) / 256, 256>>>(proj1_w, w1, CH * CH);
    conv_kernel<<<(CH * CH / 4 + 255) / 256, 256>>>(proj2_w, w2, CH * CH);

    // 1) qkv = x @ qkv_w^T (delu fused on q,k cols)
    {
        dim3 grid(QKV_N / BNt, M_ROWS / BMt);
        gemm_mma<true, false, false><<<grid, 256, GEMM_SMEM>>>(
            x16, wq, nullptr, qkv_p,
            nullptr, nullptr, nullptr, nullptr, QKV_N, 2 * CH, 1.0f);
    }

    // 2) reductions over N
    zero_red_kernel<<<(3 * BATCH * CH + 255) / 256, 256>>>(red_p);
    {
        dim3 grid(BATCH * NHEAD, NCHUNKS);
        reduce_kernel<<<grid, 256>>>(qkv_p, y, red_p);
    }

    // 3) norm + elementwise attention -> scaled fp16 operands
    attn_kernel<<<M_ROWS, 192>>>(qkv_p, red_p, aL, aG);

    // 4) both output projections in ONE launch (blockIdx.z selects)
    {
        dim3 grid(CH / BNt, M_ROWS / BMt, 2);
        gemm_mma<false, true, true><<<grid, 256, GEMM_SMEM>>>(
            aL, w1, proj1_b, out,
            aG, w2, proj2_b, out + BNC, CH, 0, INV_ASCALE);
    }
}

// round 10
// speedup vs baseline: 7.0916x; 1.0523x over previous
#include <cuda_runtime.h>
#include <cuda_fp16.h>
#include <cstdint>
#include <math.h>

// ---------------- problem constants ----------------
#define BATCH 4
#define SEQ   4096
#define CH    768
#define NHEAD 12
#define HDIM  64
#define M_ROWS (BATCH * SEQ)          // 16384
#define QKV_N  (3 * CH)               // 2304
#define BNC   (M_ROWS * CH)
#define SCALE 0.125f
#define EPSV  1e-10f
#define KDIM  768
#define ASCALE 4096.0f
#define INV_ASCALE (1.0f / 4096.0f)

// ---------------- scratch (device globals) ----------------
__device__ float g_q[M_ROWS * CH];            // delu(q), f32
__device__ __half g_x16[M_ROWS * CH];
__device__ __half g_wq[QKV_N * CH];
__device__ __half g_w1[CH * CH], g_w2[CH * CH];
__device__ __half g_aL[M_ROWS * CH];
__device__ __half g_aG[M_ROWS * CH];
__device__ float g_red[3 * BATCH * CH];       // [kv | lkv | ksum]

// ---------------- helpers ----------------
__device__ __forceinline__ float delu_f(float x) {
    return (x >= 0.0f) ? fmaf(10.0f, x, 1.0f) : __expf(10.0f * x);
}

__device__ __forceinline__ uint32_t smem_u32(const void* p) {
    uint32_t a;
    asm("{ .reg .u64 t; cvta.to.shared.u64 t, %1; cvt.u32.u64 %0, t; }" : "=r"(a) : "l"(p));
    return a;
}

__device__ __forceinline__ void cp16(uint32_t s, const void* g) {
    asm volatile("cp.async.cg.shared.global [%0], [%1], 16;" :: "r"(s), "l"(g));
}
#define CP_COMMIT() asm volatile("cp.async.commit_group;" ::: "memory")

__device__ __forceinline__ void ldsm4(uint32_t* r, uint32_t a) {
    asm volatile("ldmatrix.sync.aligned.m8n8.x4.shared.b16 {%0,%1,%2,%3}, [%4];"
                 : "=r"(r[0]), "=r"(r[1]), "=r"(r[2]), "=r"(r[3]) : "r"(a));
}

__device__ __forceinline__ void mma16816(float* c, const uint32_t* a, const uint32_t* b) {
    asm volatile(
        "mma.sync.aligned.m16n8k16.row.col.f32.f16.f16.f32 "
        "{%0,%1,%2,%3},{%4,%5,%6,%7},{%8,%9},{%0,%1,%2,%3};"
        : "+f"(c[0]), "+f"(c[1]), "+f"(c[2]), "+f"(c[3])
        : "r"(a[0]), "r"(a[1]), "r"(a[2]), "r"(a[3]), "r"(b[0]), "r"(b[1]));
}

// ---------------- tiling ----------------
#define BMt 128
#define BNt 128
#define BKt 64
#define NKT (KDIM / BKt)             // 12
#define TILE_B 16384                 // one 128x64 fp16 tile
#define OFF_B TILE_B
#define STG (2 * TILE_B)             // 32 KB per stage
#define NSTG 3
#define GEMM_SMEM (NSTG * STG + 1024)

// ======== generic GEMM (q-part / projections) ========
template <bool DELU, bool BIAS, bool ZSEL>
__global__ void __launch_bounds__(256, 2)
gemm_mma(const __half* __restrict__ A, const __half* __restrict__ B,
         const float* __restrict__ bias, float* __restrict__ C,
         const __half* __restrict__ A2, const __half* __restrict__ B2,
         const float* __restrict__ bias2, float* __restrict__ C2,
         int Nn, float descale)
{
    if (ZSEL && blockIdx.z) { A = A2; B = B2; bias = bias2; C = C2; }

    extern __shared__ char smraw[];
    const uint32_t sbase = (smem_u32(smraw) + 1023u) & ~1023u;
    const int tid  = threadIdx.x;
    const int lane = tid & 31, wid = tid >> 5;
    const int warp_m = wid >> 2, warp_n = wid & 3;
    const int m0 = blockIdx.y * BMt, n0 = blockIdx.x * BNt;

    float acc[4][4][4];
#pragma unroll
    for (int i = 0; i < 4; i++)
#pragma unroll
        for (int j = 0; j < 4; j++)
#pragma unroll
            for (int e = 0; e < 4; e++) acc[i][j][e] = 0.0f;

    auto load_tile = [&](int kt, int s) {
        const uint32_t st = sbase + s * STG;
        const int kb = kt * BKt;
#pragma unroll
        for (int i = tid; i < 1024; i += 256) {
            const int r = i >> 3, cc = i & 7;
            uint32_t off = (uint32_t)(r * 128 + cc * 16);
            off ^= (off >> 3) & 0x70;
            cp16(st + off,         A + (size_t)(m0 + r) * KDIM + kb + cc * 8);
            cp16(st + OFF_B + off, B + (size_t)(n0 + r) * KDIM + kb + cc * 8);
        }
        CP_COMMIT();
    };

    load_tile(0, 0);
    load_tile(1, 1);

    const uint32_t arow = (uint32_t)((warp_m * 64 + (lane & 15)) * 128 + (lane >> 4) * 16);
    const uint32_t brow = (uint32_t)((warp_n * 32 + (lane & 15)) * 128 + (lane >> 4) * 16);

    for (int c = 0; c < NKT; c++) {
        const int s = c % NSTG;
        if (c == NKT - 1) asm volatile("cp.async.wait_group 0;" ::: "memory");
        else              asm volatile("cp.async.wait_group 1;" ::: "memory");
        __syncthreads();

        if (c + 2 < NKT) load_tile(c + 2, (c + 2) % NSTG);

        const uint32_t st = sbase + s * STG;
#pragma unroll
        for (int ks = 0; ks < 4; ks++) {
            const uint32_t kofs = ks * 32;
            uint32_t ah[4][4], bh[4][2];
#pragma unroll
            for (int mf = 0; mf < 4; mf++) {
                uint32_t off = arow + mf * 2048 + kofs;
                off ^= (off >> 3) & 0x70;
                ldsm4(ah[mf], st + off);
            }
#pragma unroll
            for (int g = 0; g < 2; g++) {
                uint32_t off = brow + g * 2048 + kofs;
                off ^= (off >> 3) & 0x70;
                uint32_t q[4];
                ldsm4(q, st + OFF_B + off);
                bh[g * 2][0] = q[0]; bh[g * 2][1] = q[2];
                bh[g * 2 + 1][0] = q[1]; bh[g * 2 + 1][1] = q[3];
            }
#pragma unroll
            for (int mf = 0; mf < 4; mf++)
#pragma unroll
                for (int nf = 0; nf < 4; nf++)
                    mma16816(acc[mf][nf], ah[mf], bh[nf]);
        }
    }

#pragma unroll
    for (int mf = 0; mf < 4; mf++) {
        const int row = m0 + warp_m * 64 + mf * 16 + (lane >> 2);
#pragma unroll
        for (int nf = 0; nf < 4; nf++) {
            const int col = n0 + warp_n * 32 + nf * 8 + (lane & 3) * 2;
            float v0 = acc[mf][nf][0] * descale, v1 = acc[mf][nf][1] * descale;
            float v2 = acc[mf][nf][2] * descale, v3 = acc[mf][nf][3] * descale;
            if (BIAS) {
                const float b0 = bias[col], b1 = bias[col + 1];
                v0 += b0; v1 += b1; v2 += b0; v3 += b1;
            }
            if (DELU) {
                v0 = delu_f(v0); v1 = delu_f(v1); v2 = delu_f(v2); v3 = delu_f(v3);
            }
            float2* p0 = reinterpret_cast<float2*>(C + (size_t)row * Nn + col);
            float2* p1 = reinterpret_cast<float2*>(C + (size_t)(row + 8) * Nn + col);
            *p0 = make_float2(v0, v1);
            *p1 = make_float2(v2, v3);
        }
    }
}

// ======== fused kv GEMM + diagonal reductions (no global C) ========
// CTA computes k[128 rows x 64 cols] and v[128 rows x 64 cols] for head-dim
// column group g = blockIdx.x (cols g*64..g*64+63), then reduces over rows:
//   red[kv]  += sum_r delu(k)*v ;  red[lkv] += sum_r delu(y)*v ;  red[ks] += sum_r delu(k)
__global__ void __launch_bounds__(256, 2)
gemm_kv(const __half* __restrict__ A, const __half* __restrict__ Wq,
        const float* __restrict__ y, float* __restrict__ red)
{
    extern __shared__ char smraw[];
    const uint32_t sbase = (smem_u32(smraw) + 1023u) & ~1023u;
    const int tid  = threadIdx.x;
    const int lane = tid & 31, wid = tid >> 5;
    const int warp_m = wid >> 2, warp_n = wid & 3;
    const int m0 = blockIdx.y * BMt;
    const int g64 = blockIdx.x * 64;           // head-dim col base
    const int b = m0 >> 12;                    // batch of this row tile

    float acc[4][4][4];
#pragma unroll
    for (int i = 0; i < 4; i++)
#pragma unroll
        for (int j = 0; j < 4; j++)
#pragma unroll
            for (int e = 0; e < 4; e++) acc[i][j][e] = 0.0f;

    auto load_tile = [&](int kt, int s) {
        const uint32_t st = sbase + s * STG;
        const int kb = kt * BKt;
#pragma unroll
        for (int i = tid; i < 1024; i += 256) {
            const int r = i >> 3, cc = i & 7;
            uint32_t off = (uint32_t)(r * 128 + cc * 16);
            off ^= (off >> 3) & 0x70;
            cp16(st + off, A + (size_t)(m0 + r) * KDIM + kb + cc * 8);
            // B rows: 0-63 -> k weights (wq row 768+g64+r); 64-127 -> v (1536+g64+r-64)
            const int rg = (r < 64) ? (CH + g64 + r) : (2 * CH + g64 + r - 64);
            cp16(st + OFF_B + off, Wq + (size_t)rg * KDIM + kb + cc * 8);
        }
        CP_COMMIT();
    };

    load_tile(0, 0);
    load_tile(1, 1);

    const uint32_t arow = (uint32_t)((warp_m * 64 + (lane & 15)) * 128 + (lane >> 4) * 16);
    const uint32_t brow = (uint32_t)((warp_n * 32 + (lane & 15)) * 128 + (lane >> 4) * 16);

    for (int c = 0; c < NKT; c++) {
        const int s = c % NSTG;
        if (c == NKT - 1) asm volatile("cp.async.wait_group 0;" ::: "memory");
        else              asm volatile("cp.async.wait_group 1;" ::: "memory");
        __syncthreads();

        if (c + 2 < NKT) load_tile(c + 2, (c + 2) % NSTG);

        const uint32_t st = sbase + s * STG;
#pragma unroll
        for (int ks = 0; ks < 4; ks++) {
            const uint32_t kofs = ks * 32;
            uint32_t ah[4][4], bh[4][2];
#pragma unroll
            for (int mf = 0; mf < 4; mf++) {
                uint32_t off = arow + mf * 2048 + kofs;
                off ^= (off >> 3) & 0x70;
                ldsm4(ah[mf], st + off);
            }
#pragma unroll
            for (int gg = 0; gg < 2; gg++) {
                uint32_t off = brow + gg * 2048 + kofs;
                off ^= (off >> 3) & 0x70;
                uint32_t q[4];
                ldsm4(q, st + OFF_B + off);
                bh[gg * 2][0] = q[0]; bh[gg * 2][1] = q[2];
                bh[gg * 2 + 1][0] = q[1]; bh[gg * 2 + 1][1] = q[3];
            }
#pragma unroll
            for (int mf = 0; mf < 4; mf++)
#pragma unroll
                for (int nf = 0; nf < 4; nf++)
                    mma16816(acc[mf][nf], ah[mf], bh[nf]);
        }
    }

    // ---- fused reduction epilogue ----
    // warps n=0,1 hold k cols [warp_n*32 .. +32); n=2,3 hold v cols [(warp_n-2)*32 ..)
    __syncthreads();                               // done with pipeline smem
    float* vbuf = reinterpret_cast<float*>(smraw); // [128][65] padded
    const bool is_v = (warp_n >= 2);

    if (is_v) {
#pragma unroll
        for (int mf = 0; mf < 4; mf++) {
            const int r = warp_m * 64 + mf * 16 + (lane >> 2);
#pragma unroll
            for (int nf = 0; nf < 4; nf++) {
                const int cl = (warp_n - 2) * 32 + nf * 8 + (lane & 3) * 2;
                vbuf[r * 65 + cl]       = acc[mf][nf][0];
                vbuf[r * 65 + cl + 1]   = acc[mf][nf][1];
                vbuf[(r + 8) * 65 + cl]     = acc[mf][nf][2];
                vbuf[(r + 8) * 65 + cl + 1] = acc[mf][nf][3];
            }
        }
    }
    __syncthreads();

    if (is_v) {
        // lkv[c] = sum_r delu(y[r,c]) * v[r,c]
        float s0[4], s1[4];
#pragma unroll
        for (int nf = 0; nf < 4; nf++) { s0[nf] = 0.f; s1[nf] = 0.f; }
#pragma unroll
        for (int mf = 0; mf < 4; mf++) {
            const int r = m0 + warp_m * 64 + mf * 16 + (lane >> 2);
#pragma unroll
            for (int nf = 0; nf < 4; nf++) {
                const int cg = g64 + (warp_n - 2) * 32 + nf * 8 + (lane & 3) * 2;
                const float2 ya = *reinterpret_cast<const float2*>(y + (size_t)r * CH + cg);
                const float2 yb = *reinterpret_cast<const float2*>(y + (size_t)(r + 8) * CH + cg);
                s0[nf] = fmaf(delu_f(ya.x), acc[mf][nf][0], s0[nf]);
                s1[nf] = fmaf(delu_f(ya.y), acc[mf][nf][1], s1[nf]);
                s0[nf] = fmaf(delu_f(yb.x), acc[mf][nf][2], s0[nf]);
                s1[nf] = fmaf(delu_f(yb.y), acc[mf][nf][3], s1[nf]);
            }
        }
#pragma unroll
        for (int nf = 0; nf < 4; nf++) {
#pragma unroll
            for (int off = 4; off <= 16; off <<= 1) {
                s0[nf] += __shfl_xor_sync(0xffffffffu, s0[nf], off);
                s1[nf] += __shfl_xor_sync(0xffffffffu, s1[nf], off);
            }
        }
        if (lane < 4) {
#pragma unroll
            for (int nf = 0; nf < 4; nf++) {
                const int cg = g64 + (warp_n - 2) * 32 + nf * 8 + lane * 2;
                atomicAdd(&red[BATCH * CH + b * CH + cg],     s0[nf]);
                atomicAdd(&red[BATCH * CH + b * CH + cg + 1], s1[nf]);
            }
        }
    } else {
        // kv[c] = sum_r delu(k)*v ; ks[c] = sum_r delu(k)
        float p0[4], p1[4], k0[4], k1[4];
#pragma unroll
        for (int nf = 0; nf < 4; nf++) { p0[nf] = p1[nf] = k0[nf] = k1[nf] = 0.f; }
#pragma unroll
        for (int mf = 0; mf < 4; mf++) {
            const int r = warp_m * 64 + mf * 16 + (lane >> 2);
#pragma unroll
            for (int nf = 0; nf < 4; nf++) {
                const int cl = warp_n * 32 + nf * 8 + (lane & 3) * 2;
                const float ka = delu_f(acc[mf][nf][0]);
                const float kb = delu_f(acc[mf][nf][1]);
                const float kc = delu_f(acc[mf][nf][2]);
                const float kd = delu_f(acc[mf][nf][3]);
                p0[nf] = fmaf(ka, vbuf[r * 65 + cl],           p0[nf]);
                p1[nf] = fmaf(kb, vbuf[r * 65 + cl + 1],       p1[nf]);
                p0[nf] = fmaf(kc, vbuf[(r + 8) * 65 + cl],     p0[nf]);
                p1[nf] = fmaf(kd, vbuf[(r + 8) * 65 + cl + 1], p1[nf]);
                k0[nf] += ka + kc;
                k1[nf] += kb + kd;
            }
        }
#pragma unroll
        for (int nf = 0; nf < 4; nf++) {
#pragma unroll
            for (int off = 4; off <= 16; off <<= 1) {
                p0[nf] += __shfl_xor_sync(0xffffffffu, p0[nf], off);
                p1[nf] += __shfl_xor_sync(0xffffffffu, p1[nf], off);
                k0[nf] += __shfl_xor_sync(0xffffffffu, k0[nf], off);
                k1[nf] += __shfl_xor_sync(0xffffffffu, k1[nf], off);
            }
        }
        if (lane < 4) {
#pragma unroll
            for (int nf = 0; nf < 4; nf++) {
                const int cg = g64 + warp_n * 32 + nf * 8 + lane * 2;
                atomicAdd(&red[b * CH + cg],     p0[nf]);
                atomicAdd(&red[b * CH + cg + 1], p1[nf]);
                atomicAdd(&red[2 * BATCH * CH + b * CH + cg],     k0[nf]);
                atomicAdd(&red[2 * BATCH * CH + b * CH + cg + 1], k1[nf]);
            }
        }
    }
}

// ---------------- f32 -> fp16 convert ----------------
__global__ void conv_kernel(const float* __restrict__ src, __half* __restrict__ dst, int n)
{
    int i = (blockIdx.x * blockDim.x + threadIdx.x) * 4;
    if (i >= n) return;
    float4 v = *reinterpret_cast<const float4*>(src + i);
    __half2* D = reinterpret_cast<__half2*>(dst + i);
    D[0] = __halves2half2(__float2half(v.x), __float2half(v.y));
    D[1] = __halves2half2(__float2half(v.z), __float2half(v.w));
}

// ---------------- zero reduction accumulators ----------------
__global__ void zero_red_kernel(float* __restrict__ red) {
    int i = blockIdx.x * blockDim.x + threadIdx.x;
    if (i < 3 * BATCH * CH) red[i] = 0.0f;
}

// ---------------- norm + attn: 192 thr/row, float4, no smem ----------------
__global__ void __launch_bounds__(192)
attn_kernel(const float* __restrict__ qbuf, const float* __restrict__ red,
            __half* __restrict__ oL, __half* __restrict__ oG)
{
    const int bn = blockIdx.x;             // 0..16383
    const int b  = bn >> 12;
    const int t  = threadIdx.x;            // 0..191
    const int h  = t >> 4;                 // 0..11
    const int p  = t & 15;
    const int c0 = h * HDIM + p * 4;

    const float4 q = *reinterpret_cast<const float4*>(qbuf + (size_t)bn * CH + c0);
    const float4 ks = *reinterpret_cast<const float4*>(red + 2 * BATCH * CH + b * CH + c0);

    float pp = q.x * (ks.x + EPSV) + q.y * (ks.y + EPSV)
             + q.z * (ks.z + EPSV) + q.w * (ks.w + EPSV);
#pragma unroll
    for (int off = 8; off; off >>= 1)
        pp += __shfl_xor_sync(0xffffffffu, pp, off, 16);

    const float norm = ASCALE / pp;
    const float4 kvd  = *reinterpret_cast<const float4*>(red + b * CH + c0);
    const float4 lkvd = *reinterpret_cast<const float4*>(red + BATCH * CH + b * CH + c0);

    const size_t idx = (size_t)bn * CH + c0;
    __half2* L = reinterpret_cast<__half2*>(oL + idx);
    __half2* G = reinterpret_cast<__half2*>(oG + idx);
    const float sn = SCALE * norm;
    L[0] = __halves2half2(__float2half(q.x * kvd.x * sn),  __float2half(q.y * kvd.y * sn));
    L[1] = __halves2half2(__float2half(q.z * kvd.z * sn),  __float2half(q.w * kvd.w * sn));
    G[0] = __halves2half2(__float2half(q.x * lkvd.x * sn), __float2half(q.y * lkvd.y * sn));
    G[1] = __halves2half2(__float2half(q.z * lkvd.z * sn), __float2half(q.w * lkvd.w * sn));
}

// ---------------- launch ----------------
extern "C" void kernel_launch(void* const* d_in, const int* in_sizes, int n_in,
                              void* d_out, int out_size)
{
    const float* x       = (const float*)d_in[0];
    const float* y       = (const float*)d_in[1];
    const float* qkv_w   = (const float*)d_in[2];
    const float* proj1_w = (const float*)d_in[3];
    const float* proj1_b = (const float*)d_in[4];
    const float* proj2_w = (const float*)d_in[5];
    const float* proj2_b = (const float*)d_in[6];
    float* out = (float*)d_out;

    float *q_p, *red_p;
    __half *x16, *wq, *w1, *w2, *aL, *aG;
    cudaGetSymbolAddress((void**)&q_p, g_q);
    cudaGetSymbolAddress((void**)&red_p, g_red);
    cudaGetSymbolAddress((void**)&x16, g_x16);
    cudaGetSymbolAddress((void**)&wq, g_wq);
    cudaGetSymbolAddress((void**)&w1, g_w1);   cudaGetSymbolAddress((void**)&w2, g_w2);
    cudaGetSymbolAddress((void**)&aL, g_aL);   cudaGetSymbolAddress((void**)&aG, g_aG);

    cudaFuncSetAttribute(gemm_mma<true, false, false>,
                         cudaFuncAttributeMaxDynamicSharedMemorySize, GEMM_SMEM);
    cudaFuncSetAttribute(gemm_mma<false, true, true>,
                         cudaFuncAttributeMaxDynamicSharedMemorySize, GEMM_SMEM);
    cudaFuncSetAttribute(gemm_kv,
                         cudaFuncAttributeMaxDynamicSharedMemorySize, GEMM_SMEM);

    // 0) convert x and weights to fp16; zero accumulators
    conv_kernel<<<(M_ROWS * CH / 4 + 255) / 256, 256>>>(x, x16, M_ROWS * CH);
    conv_kernel<<<(QKV_N * CH / 4 + 255) / 256, 256>>>(qkv_w, wq, QKV_N * CH);
    conv_kernel<<<(CH * CH / 4 + 255) / 256, 256>>>(proj1_w, w1, CH * CH);
    conv_kernel<<<(CH * CH / 4 + 255) / 256, 256>>>(proj2_w, w2, CH * CH);
    zero_red_kernel<<<(3 * BATCH * CH + 255) / 256, 256>>>(red_p);

    // 1a) q = delu(x @ Wq_q^T) -> g_q (f32)
    {
        dim3 grid(CH / BNt, M_ROWS / BMt);
        gemm_mma<true, false, false><<<grid, 256, GEMM_SMEM>>>(
            x16, wq, nullptr, q_p,
            nullptr, nullptr, nullptr, nullptr, CH, 1.0f);
    }

    // 1b) fused k/v GEMM + diagonal reductions (no k/v materialization)
    {
        dim3 grid(CH / 64, M_ROWS / BMt);
        gemm_kv<<<grid, 256, GEMM_SMEM>>>(x16, wq, y, red_p);
    }

    // 2) norm + elementwise attention -> scaled fp16 operands
    attn_kernel<<<M_ROWS, 192>>>(q_p, red_p, aL, aG);

    // 3) both output projections in ONE launch (blockIdx.z selects)
    {
        dim3 grid(CH / BNt, M_ROWS / BMt, 2);
        gemm_mma<false, true, true><<<grid, 256, GEMM_SMEM>>>(
            aL, w1, proj1_b, out,
            aG, w2, proj2_b, out + BNC, CH, 1.0f * INV_ASCALE);
    }
}

// round 11
// speedup vs baseline: 7.1244x; 1.0046x over previous
#include <cuda_runtime.h>
#include <cuda_fp16.h>
#include <cstdint>
#include <math.h>

// ---------------- problem constants ----------------
#define BATCH 4
#define SEQ   4096
#define CH    768
#define NHEAD 12
#define HDIM  64
#define M_ROWS (BATCH * SEQ)          // 16384
#define QKV_N  (3 * CH)               // 2304
#define BNC   (M_ROWS * CH)
#define SCALE 0.125f
#define EPSV  1e-10f
#define KDIM  768
#define ASCALE 4096.0f
#define INV_ASCALE (1.0f / 4096.0f)

// ---------------- scratch (device globals) ----------------
__device__ __half g_x16[M_ROWS * CH];
__device__ __half g_wq[QKV_N * CH];
__device__ __half g_w1[CH * CH], g_w2[CH * CH];
__device__ __half g_aL[M_ROWS * CH];
__device__ __half g_aG[M_ROWS * CH];
__device__ float g_red[3 * BATCH * CH];       // [kv | lkv | ksum]

// ---------------- helpers ----------------
__device__ __forceinline__ float delu_f(float x) {
    return (x >= 0.0f) ? fmaf(10.0f, x, 1.0f) : __expf(10.0f * x);
}

__device__ __forceinline__ uint32_t smem_u32(const void* p) {
    uint32_t a;
    asm("{ .reg .u64 t; cvta.to.shared.u64 t, %1; cvt.u32.u64 %0, t; }" : "=r"(a) : "l"(p));
    return a;
}

__device__ __forceinline__ void cp16(uint32_t s, const void* g) {
    asm volatile("cp.async.cg.shared.global [%0], [%1], 16;" :: "r"(s), "l"(g));
}
#define CP_COMMIT() asm volatile("cp.async.commit_group;" ::: "memory")

__device__ __forceinline__ void ldsm4(uint32_t* r, uint32_t a) {
    asm volatile("ldmatrix.sync.aligned.m8n8.x4.shared.b16 {%0,%1,%2,%3}, [%4];"
                 : "=r"(r[0]), "=r"(r[1]), "=r"(r[2]), "=r"(r[3]) : "r"(a));
}

__device__ __forceinline__ void mma16816(float* c, const uint32_t* a, const uint32_t* b) {
    asm volatile(
        "mma.sync.aligned.m16n8k16.row.col.f32.f16.f16.f32 "
        "{%0,%1,%2,%3},{%4,%5,%6,%7},{%8,%9},{%0,%1,%2,%3};"
        : "+f"(c[0]), "+f"(c[1]), "+f"(c[2]), "+f"(c[3])
        : "r"(a[0]), "r"(a[1]), "r"(a[2]), "r"(a[3]), "r"(b[0]), "r"(b[1]));
}

// ---------------- tiling ----------------
#define BMt 128
#define BNt 128
#define BKt 64
#define NKT (KDIM / BKt)             // 12
#define TILE_B 16384
#define OFF_B TILE_B
#define STG (2 * TILE_B)             // 32 KB per stage
#define NSTG 3
#define GEMM_SMEM (NSTG * STG + 1024)

// shared mainloop body (accumulates A[m0:+128,768] @ B'[n-tile,768]^T)
#define GEMM_MAINLOOP(LOADFN)                                                 \
    LOADFN(0, 0);                                                             \
    LOADFN(1, 1);                                                             \
    const uint32_t arow = (uint32_t)((warp_m * 64 + (lane & 15)) * 128 + (lane >> 4) * 16); \
    const uint32_t brow = (uint32_t)((warp_n * 32 + (lane & 15)) * 128 + (lane >> 4) * 16); \
    for (int c = 0; c < NKT; c++) {                                           \
        const int s = c % NSTG;                                               \
        if (c == NKT - 1) asm volatile("cp.async.wait_group 0;" ::: "memory");\
        else              asm volatile("cp.async.wait_group 1;" ::: "memory");\
        __syncthreads();                                                      \
        if (c + 2 < NKT) LOADFN(c + 2, (c + 2) % NSTG);                       \
        const uint32_t st = sbase + s * STG;                                  \
        _Pragma("unroll")                                                     \
        for (int ks = 0; ks < 4; ks++) {                                      \
            const uint32_t kofs = ks * 32;                                    \
            uint32_t ah[4][4], bh[4][2];                                      \
            _Pragma("unroll")                                                 \
            for (int mf = 0; mf < 4; mf++) {                                  \
                uint32_t off = arow + mf * 2048 + kofs;                       \
                off ^= (off >> 3) & 0x70;                                     \
                ldsm4(ah[mf], st + off);                                      \
            }                                                                 \
            _Pragma("unroll")                                                 \
            for (int gg = 0; gg < 2; gg++) {                                  \
                uint32_t off = brow + gg * 2048 + kofs;                       \
                off ^= (off >> 3) & 0x70;                                     \
                uint32_t qq[4];                                               \
                ldsm4(qq, st + OFF_B + off);                                  \
                bh[gg * 2][0] = qq[0]; bh[gg * 2][1] = qq[2];                 \
                bh[gg * 2 + 1][0] = qq[1]; bh[gg * 2 + 1][1] = qq[3];         \
            }                                                                 \
            _Pragma("unroll")                                                 \
            for (int mf = 0; mf < 4; mf++)                                    \
                _Pragma("unroll")                                             \
                for (int nf = 0; nf < 4; nf++)                                \
                    mma16816(acc[mf][nf], ah[mf], bh[nf]);                    \
        }                                                                     \
    }

// ======== projection GEMM (both proj in one launch via blockIdx.z) ========
__global__ void __launch_bounds__(256, 2)
gemm_proj(const __half* __restrict__ A, const __half* __restrict__ B,
          const float* __restrict__ bias, float* __restrict__ C,
          const __half* __restrict__ A2, const __half* __restrict__ B2,
          const float* __restrict__ bias2, float* __restrict__ C2)
{
    if (blockIdx.z) { A = A2; B = B2; bias = bias2; C = C2; }

    extern __shared__ char smraw[];
    const uint32_t sbase = (smem_u32(smraw) + 1023u) & ~1023u;
    const int tid = threadIdx.x;
    const int lane = tid & 31, wid = tid >> 5;
    const int warp_m = wid >> 2, warp_n = wid & 3;
    const int m0 = blockIdx.y * BMt, n0 = blockIdx.x * BNt;

    float acc[4][4][4];
#pragma unroll
    for (int i = 0; i < 4; i++)
#pragma unroll
        for (int j = 0; j < 4; j++)
#pragma unroll
            for (int e = 0; e < 4; e++) acc[i][j][e] = 0.0f;

    auto load_tile = [&](int kt, int s) {
        const uint32_t st = sbase + s * STG;
        const int kb = kt * BKt;
#pragma unroll
        for (int i = tid; i < 1024; i += 256) {
            const int r = i >> 3, cc = i & 7;
            uint32_t off = (uint32_t)(r * 128 + cc * 16);
            off ^= (off >> 3) & 0x70;
            cp16(st + off,         A + (size_t)(m0 + r) * KDIM + kb + cc * 8);
            cp16(st + OFF_B + off, B + (size_t)(n0 + r) * KDIM + kb + cc * 8);
        }
        CP_COMMIT();
    };

    GEMM_MAINLOOP(load_tile)

#pragma unroll
    for (int mf = 0; mf < 4; mf++) {
        const int row = m0 + warp_m * 64 + mf * 16 + (lane >> 2);
#pragma unroll
        for (int nf = 0; nf < 4; nf++) {
            const int col = n0 + warp_n * 32 + nf * 8 + (lane & 3) * 2;
            const float b0 = bias[col], b1 = bias[col + 1];
            float v0 = fmaf(acc[mf][nf][0], INV_ASCALE, b0);
            float v1 = fmaf(acc[mf][nf][1], INV_ASCALE, b1);
            float v2 = fmaf(acc[mf][nf][2], INV_ASCALE, b0);
            float v3 = fmaf(acc[mf][nf][3], INV_ASCALE, b1);
            float2* p0 = reinterpret_cast<float2*>(C + (size_t)row * CH + col);
            float2* p1 = reinterpret_cast<float2*>(C + (size_t)(row + 8) * CH + col);
            *p0 = make_float2(v0, v1);
            *p1 = make_float2(v2, v3);
        }
    }
}

// ======== fused kv GEMM + diagonal reductions (no global C) ========
__global__ void __launch_bounds__(256, 2)
gemm_kv(const __half* __restrict__ A, const __half* __restrict__ Wq,
        const float* __restrict__ y, float* __restrict__ red)
{
    extern __shared__ char smraw[];
    const uint32_t sbase = (smem_u32(smraw) + 1023u) & ~1023u;
    const int tid = threadIdx.x;
    const int lane = tid & 31, wid = tid >> 5;
    const int warp_m = wid >> 2, warp_n = wid & 3;
    const int m0 = blockIdx.y * BMt;
    const int g64 = blockIdx.x * 64;
    const int b = m0 >> 12;

    float acc[4][4][4];
#pragma unroll
    for (int i = 0; i < 4; i++)
#pragma unroll
        for (int j = 0; j < 4; j++)
#pragma unroll
            for (int e = 0; e < 4; e++) acc[i][j][e] = 0.0f;

    auto load_tile = [&](int kt, int s) {
        const uint32_t st = sbase + s * STG;
        const int kb = kt * BKt;
#pragma unroll
        for (int i = tid; i < 1024; i += 256) {
            const int r = i >> 3, cc = i & 7;
            uint32_t off = (uint32_t)(r * 128 + cc * 16);
            off ^= (off >> 3) & 0x70;
            cp16(st + off, A + (size_t)(m0 + r) * KDIM + kb + cc * 8);
            const int rg = (r < 64) ? (CH + g64 + r) : (2 * CH + g64 + r - 64);
            cp16(st + OFF_B + off, Wq + (size_t)rg * KDIM + kb + cc * 8);
        }
        CP_COMMIT();
    };

    GEMM_MAINLOOP(load_tile)

    __syncthreads();
    float* vbuf = reinterpret_cast<float*>(smraw); // [128][65]
    const bool is_v = (warp_n >= 2);

    if (is_v) {
#pragma unroll
        for (int mf = 0; mf < 4; mf++) {
            const int r = warp_m * 64 + mf * 16 + (lane >> 2);
#pragma unroll
            for (int nf = 0; nf < 4; nf++) {
                const int cl = (warp_n - 2) * 32 + nf * 8 + (lane & 3) * 2;
                vbuf[r * 65 + cl]           = acc[mf][nf][0];
                vbuf[r * 65 + cl + 1]       = acc[mf][nf][1];
                vbuf[(r + 8) * 65 + cl]     = acc[mf][nf][2];
                vbuf[(r + 8) * 65 + cl + 1] = acc[mf][nf][3];
            }
        }
    }
    __syncthreads();

    if (is_v) {
        float s0[4], s1[4];
#pragma unroll
        for (int nf = 0; nf < 4; nf++) { s0[nf] = 0.f; s1[nf] = 0.f; }
#pragma unroll
        for (int mf = 0; mf < 4; mf++) {
            const int r = m0 + warp_m * 64 + mf * 16 + (lane >> 2);
#pragma unroll
            for (int nf = 0; nf < 4; nf++) {
                const int cg = g64 + (warp_n - 2) * 32 + nf * 8 + (lane & 3) * 2;
                const float2 ya = *reinterpret_cast<const float2*>(y + (size_t)r * CH + cg);
                const float2 yb = *reinterpret_cast<const float2*>(y + (size_t)(r + 8) * CH + cg);
                s0[nf] = fmaf(delu_f(ya.x), acc[mf][nf][0], s0[nf]);
                s1[nf] = fmaf(delu_f(ya.y), acc[mf][nf][1], s1[nf]);
                s0[nf] = fmaf(delu_f(yb.x), acc[mf][nf][2], s0[nf]);
                s1[nf] = fmaf(delu_f(yb.y), acc[mf][nf][3], s1[nf]);
            }
        }
#pragma unroll
        for (int nf = 0; nf < 4; nf++) {
#pragma unroll
            for (int off = 4; off <= 16; off <<= 1) {
                s0[nf] += __shfl_xor_sync(0xffffffffu, s0[nf], off);
                s1[nf] += __shfl_xor_sync(0xffffffffu, s1[nf], off);
            }
        }
        if (lane < 4) {
#pragma unroll
            for (int nf = 0; nf < 4; nf++) {
                const int cg = g64 + (warp_n - 2) * 32 + nf * 8 + lane * 2;
                atomicAdd(&red[BATCH * CH + b * CH + cg],     s0[nf]);
                atomicAdd(&red[BATCH * CH + b * CH + cg + 1], s1[nf]);
            }
        }
    } else {
        float p0[4], p1[4], k0[4], k1[4];
#pragma unroll
        for (int nf = 0; nf < 4; nf++) { p0[nf] = p1[nf] = k0[nf] = k1[nf] = 0.f; }
#pragma unroll
        for (int mf = 0; mf < 4; mf++) {
            const int r = warp_m * 64 + mf * 16 + (lane >> 2);
#pragma unroll
            for (int nf = 0; nf < 4; nf++) {
                const int cl = warp_n * 32 + nf * 8 + (lane & 3) * 2;
                const float ka = delu_f(acc[mf][nf][0]);
                const float kb = delu_f(acc[mf][nf][1]);
                const float kc = delu_f(acc[mf][nf][2]);
                const float kd = delu_f(acc[mf][nf][3]);
                p0[nf] = fmaf(ka, vbuf[r * 65 + cl],           p0[nf]);
                p1[nf] = fmaf(kb, vbuf[r * 65 + cl + 1],       p1[nf]);
                p0[nf] = fmaf(kc, vbuf[(r + 8) * 65 + cl],     p0[nf]);
                p1[nf] = fmaf(kd, vbuf[(r + 8) * 65 + cl + 1], p1[nf]);
                k0[nf] += ka + kc;
                k1[nf] += kb + kd;
            }
        }
#pragma unroll
        for (int nf = 0; nf < 4; nf++) {
#pragma unroll
            for (int off = 4; off <= 16; off <<= 1) {
                p0[nf] += __shfl_xor_sync(0xffffffffu, p0[nf], off);
                p1[nf] += __shfl_xor_sync(0xffffffffu, p1[nf], off);
                k0[nf] += __shfl_xor_sync(0xffffffffu, k0[nf], off);
                k1[nf] += __shfl_xor_sync(0xffffffffu, k1[nf], off);
            }
        }
        if (lane < 4) {
#pragma unroll
            for (int nf = 0; nf < 4; nf++) {
                const int cg = g64 + warp_n * 32 + nf * 8 + lane * 2;
                atomicAdd(&red[b * CH + cg],     p0[nf]);
                atomicAdd(&red[b * CH + cg + 1], p1[nf]);
                atomicAdd(&red[2 * BATCH * CH + b * CH + cg],     k0[nf]);
                atomicAdd(&red[2 * BATCH * CH + b * CH + cg + 1], k1[nf]);
            }
        }
    }
}

// ======== fused q GEMM + norm + attention elementwise (reads red) ========
// Requires gemm_kv complete. Writes aL/aG fp16 (scaled by ASCALE) directly.
__global__ void __launch_bounds__(256, 2)
gemm_q_attn(const __half* __restrict__ A, const __half* __restrict__ Wq,
            const float* __restrict__ red,
            __half* __restrict__ oL, __half* __restrict__ oG)
{
    extern __shared__ char smraw[];
    const uint32_t sbase = (smem_u32(smraw) + 1023u) & ~1023u;
    const int tid = threadIdx.x;
    const int lane = tid & 31, wid = tid >> 5;
    const int warp_m = wid >> 2, warp_n = wid & 3;
    const int m0 = blockIdx.y * BMt, n0 = blockIdx.x * BNt;
    const int b = m0 >> 12;

    float acc[4][4][4];
#pragma unroll
    for (int i = 0; i < 4; i++)
#pragma unroll
        for (int j = 0; j < 4; j++)
#pragma unroll
            for (int e = 0; e < 4; e++) acc[i][j][e] = 0.0f;

    auto load_tile = [&](int kt, int s) {
        const uint32_t st = sbase + s * STG;
        const int kb = kt * BKt;
#pragma unroll
        for (int i = tid; i < 1024; i += 256) {
            const int r = i >> 3, cc = i & 7;
            uint32_t off = (uint32_t)(r * 128 + cc * 16);
            off ^= (off >> 3) & 0x70;
            cp16(st + off,         A + (size_t)(m0 + r) * KDIM + kb + cc * 8);
            cp16(st + OFF_B + off, Wq + (size_t)(n0 + r) * KDIM + kb + cc * 8);
        }
        CP_COMMIT();
    };

    GEMM_MAINLOOP(load_tile)

    // ---- fused attention epilogue ----
    // 1) delu; 2) per-(row, head) norm via quad-shuffle + smem pair exchange;
    // 3) write aL/aG fp16.
    const float* ksb  = red + 2 * BATCH * CH + b * CH;
    const float* kvb  = red + b * CH;
    const float* lkvb = red + BATCH * CH + b * CH;

    float ks0[4], ks1[4], kv0[4], kv1[4], lk0[4], lk1[4];
#pragma unroll
    for (int nf = 0; nf < 4; nf++) {
        const int col = n0 + warp_n * 32 + nf * 8 + (lane & 3) * 2;
        ks0[nf] = ksb[col] + EPSV;       ks1[nf] = ksb[col + 1] + EPSV;
        kv0[nf] = kvb[col] * SCALE;      kv1[nf] = kvb[col + 1] * SCALE;
        lk0[nf] = lkvb[col] * SCALE;     lk1[nf] = lkvb[col + 1] * SCALE;
    }

#pragma unroll
    for (int mf = 0; mf < 4; mf++)
#pragma unroll
        for (int nf = 0; nf < 4; nf++)
#pragma unroll
            for (int e = 0; e < 4; e++) acc[mf][nf][e] = delu_f(acc[mf][nf][e]);

    __syncthreads();                               // pipeline smem free
    float (*psum)[128] = reinterpret_cast<float (*)[128]>(smraw); // [4][128]

#pragma unroll
    for (int mf = 0; mf < 4; mf++) {
        float pa = 0.f, pb = 0.f;
#pragma unroll
        for (int nf = 0; nf < 4; nf++) {
            pa += acc[mf][nf][0] * ks0[nf] + acc[mf][nf][1] * ks1[nf];
            pb += acc[mf][nf][2] * ks0[nf] + acc[mf][nf][3] * ks1[nf];
        }
        pa += __shfl_xor_sync(0xffffffffu, pa, 1);
        pa += __shfl_xor_sync(0xffffffffu, pa, 2);
        pb += __shfl_xor_sync(0xffffffffu, pb, 1);
        pb += __shfl_xor_sync(0xffffffffu, pb, 2);
        if ((lane & 3) == 0) {
            const int rl = warp_m * 64 + mf * 16 + (lane >> 2);
            psum[warp_n][rl]     = pa;
            psum[warp_n][rl + 8] = pb;
        }
    }
    __syncthreads();

    const int hw = warp_n & ~1;                    // partner-pair base for this head
#pragma unroll
    for (int mf = 0; mf < 4; mf++) {
        const int rl = warp_m * 64 + mf * 16 + (lane >> 2);
        const float na = ASCALE / (psum[hw][rl]     + psum[hw + 1][rl]);
        const float nb = ASCALE / (psum[hw][rl + 8] + psum[hw + 1][rl + 8]);
        const int row = m0 + rl;
#pragma unroll
        for (int nf = 0; nf < 4; nf++) {
            const int col = n0 + warp_n * 32 + nf * 8 + (lane & 3) * 2;
            const size_t i0 = (size_t)row * CH + col;
            const size_t i1 = (size_t)(row + 8) * CH + col;
            *reinterpret_cast<__half2*>(oL + i0) = __halves2half2(
                __float2half(acc[mf][nf][0] * kv0[nf] * na),
                __float2half(acc[mf][nf][1] * kv1[nf] * na));
            *reinterpret_cast<__half2*>(oL + i1) = __halves2half2(
                __float2half(acc[mf][nf][2] * kv0[nf] * nb),
                __float2half(acc[mf][nf][3] * kv1[nf] * nb));
            *reinterpret_cast<__half2*>(oG + i0) = __halves2half2(
                __float2half(acc[mf][nf][0] * lk0[nf] * na),
                __float2half(acc[mf][nf][1] * lk1[nf] * na));
            *reinterpret_cast<__half2*>(oG + i1) = __halves2half2(
                __float2half(acc[mf][nf][2] * lk0[nf] * nb),
                __float2half(acc[mf][nf][3] * lk1[nf] * nb));
        }
    }
}

// ---------------- f32 -> fp16 convert ----------------
__global__ void conv_kernel(const float* __restrict__ src, __half* __restrict__ dst, int n)
{
    int i = (blockIdx.x * blockDim.x + threadIdx.x) * 4;
    if (i >= n) return;
    float4 v = *reinterpret_cast<const float4*>(src + i);
    __half2* D = reinterpret_cast<__half2*>(dst + i);
    D[0] = __halves2half2(__float2half(v.x), __float2half(v.y));
    D[1] = __halves2half2(__float2half(v.z), __float2half(v.w));
}

// ---------------- zero reduction accumulators ----------------
__global__ void zero_red_kernel(float* __restrict__ red) {
    int i = blockIdx.x * blockDim.x + threadIdx.x;
    if (i < 3 * BATCH * CH) red[i] = 0.0f;
}

// ---------------- launch ----------------
extern "C" void kernel_launch(void* const* d_in, const int* in_sizes, int n_in,
                              void* d_out, int out_size)
{
    const float* x       = (const float*)d_in[0];
    const float* y       = (const float*)d_in[1];
    const float* qkv_w   = (const float*)d_in[2];
    const float* proj1_w = (const float*)d_in[3];
    const float* proj1_b = (const float*)d_in[4];
    const float* proj2_w = (const float*)d_in[5];
    const float* proj2_b = (const float*)d_in[6];
    float* out = (float*)d_out;

    float* red_p;
    __half *x16, *wq, *w1, *w2, *aL, *aG;
    cudaGetSymbolAddress((void**)&red_p, g_red);
    cudaGetSymbolAddress((void**)&x16, g_x16);
    cudaGetSymbolAddress((void**)&wq, g_wq);
    cudaGetSymbolAddress((void**)&w1, g_w1);   cudaGetSymbolAddress((void**)&w2, g_w2);
    cudaGetSymbolAddress((void**)&aL, g_aL);   cudaGetSymbolAddress((void**)&aG, g_aG);

    cudaFuncSetAttribute(gemm_proj,
                         cudaFuncAttributeMaxDynamicSharedMemorySize, GEMM_SMEM);
    cudaFuncSetAttribute(gemm_kv,
                         cudaFuncAttributeMaxDynamicSharedMemorySize, GEMM_SMEM);
    cudaFuncSetAttribute(gemm_q_attn,
                         cudaFuncAttributeMaxDynamicSharedMemorySize, GEMM_SMEM);

    // 0) convert x and weights to fp16; zero accumulators
    conv_kernel<<<(M_ROWS * CH / 4 + 255) / 256, 256>>>(x, x16, M_ROWS * CH);
    conv_kernel<<<(QKV_N * CH / 4 + 255) / 256, 256>>>(qkv_w, wq, QKV_N * CH);
    conv_kernel<<<(CH * CH / 4 + 255) / 256, 256>>>(proj1_w, w1, CH * CH);
    conv_kernel<<<(CH * CH / 4 + 255) / 256, 256>>>(proj2_w, w2, CH * CH);
    zero_red_kernel<<<(3 * BATCH * CH + 255) / 256, 256>>>(red_p);

    // 1) fused k/v GEMM + diagonal reductions (must precede q GEMM)
    {
        dim3 grid(CH / 64, M_ROWS / BMt);
        gemm_kv<<<grid, 256, GEMM_SMEM>>>(x16, wq, y, red_p);
    }

    // 2) fused q GEMM + norm + attention elementwise -> aL/aG fp16
    {
        dim3 grid(CH / BNt, M_ROWS / BMt);
        gemm_q_attn<<<grid, 256, GEMM_SMEM>>>(x16, wq, red_p, aL, aG);
    }

    // 3) both output projections in ONE launch (blockIdx.z selects)
    {
        dim3 grid(CH / BNt, M_ROWS / BMt, 2);
        gemm_proj<<<grid, 256, GEMM_SMEM>>>(
            aL, w1, proj1_b, out,
            aG, w2, proj2_b, out + BNC);
    }
}

// round 12
// speedup vs baseline: 7.4932x; 1.0518x over previous
#include <cuda_runtime.h>
#include <cuda_fp16.h>
#include <cstdint>
#include <math.h>

// ---------------- problem constants ----------------
#define BATCH 4
#define SEQ   4096
#define CH    768
#define NHEAD 12
#define HDIM  64
#define M_ROWS (BATCH * SEQ)          // 16384
#define QKV_N  (3 * CH)               // 2304
#define BNC   (M_ROWS * CH)
#define SCALE 0.125f
#define EPSV  1e-10f
#define KDIM  768
#define ASCALE 4096.0f
#define INV_ASCALE (1.0f / 4096.0f)
#define KV_CTAS 1536                  // 12 * 128

// ---------------- scratch (device globals) ----------------
__device__ __half g_x16[M_ROWS * CH];
__device__ __half g_wq[QKV_N * CH];
__device__ __half g_w1[CH * CH], g_w2[CH * CH];
__device__ __half g_aL[M_ROWS * CH];
__device__ __half g_aG[M_ROWS * CH];
__device__ float g_red[3 * BATCH * CH];       // [kv | lkv | ksum]
__device__ int   g_cnt;

// ---------------- helpers ----------------
__device__ __forceinline__ float delu_f(float x) {
    return (x >= 0.0f) ? fmaf(10.0f, x, 1.0f) : __expf(10.0f * x);
}

__device__ __forceinline__ uint32_t smem_u32(const void* p) {
    uint32_t a;
    asm("{ .reg .u64 t; cvta.to.shared.u64 t, %1; cvt.u32.u64 %0, t; }" : "=r"(a) : "l"(p));
    return a;
}

__device__ __forceinline__ void cp16(uint32_t s, const void* g) {
    asm volatile("cp.async.cg.shared.global [%0], [%1], 16;" :: "r"(s), "l"(g));
}
#define CP_COMMIT() asm volatile("cp.async.commit_group;" ::: "memory")

__device__ __forceinline__ void ldsm4(uint32_t* r, uint32_t a) {
    asm volatile("ldmatrix.sync.aligned.m8n8.x4.shared.b16 {%0,%1,%2,%3}, [%4];"
                 : "=r"(r[0]), "=r"(r[1]), "=r"(r[2]), "=r"(r[3]) : "r"(a));
}

__device__ __forceinline__ void mma16816(float* c, const uint32_t* a, const uint32_t* b) {
    asm volatile(
        "mma.sync.aligned.m16n8k16.row.col.f32.f16.f16.f32 "
        "{%0,%1,%2,%3},{%4,%5,%6,%7},{%8,%9},{%0,%1,%2,%3};"
        : "+f"(c[0]), "+f"(c[1]), "+f"(c[2]), "+f"(c[3])
        : "r"(a[0]), "r"(a[1]), "r"(a[2]), "r"(a[3]), "r"(b[0]), "r"(b[1]));
}

// ---------------- tiling ----------------
#define BMt 128
#define BNt 128
#define BKt 64
#define NKT (KDIM / BKt)             // 12
#define TILE_B 16384
#define OFF_B TILE_B
#define STG (2 * TILE_B)             // 32 KB per stage
#define NSTG 3
#define GEMM_SMEM (NSTG * STG + 1024)

#define GEMM_MAINLOOP(LOADFN)                                                 \
    LOADFN(0, 0);                                                             \
    LOADFN(1, 1);                                                             \
    const uint32_t arow = (uint32_t)((warp_m * 64 + (lane & 15)) * 128 + (lane >> 4) * 16); \
    const uint32_t brow = (uint32_t)((warp_n * 32 + (lane & 15)) * 128 + (lane >> 4) * 16); \
    for (int c = 0; c < NKT; c++) {                                           \
        const int s = c % NSTG;                                               \
        if (c == NKT - 1) asm volatile("cp.async.wait_group 0;" ::: "memory");\
        else              asm volatile("cp.async.wait_group 1;" ::: "memory");\
        __syncthreads();                                                      \
        if (c + 2 < NKT) LOADFN(c + 2, (c + 2) % NSTG);                       \
        const uint32_t st = sbase + s * STG;                                  \
        _Pragma("unroll")                                                     \
        for (int ks = 0; ks < 4; ks++) {                                      \
            const uint32_t kofs = ks * 32;                                    \
            uint32_t ah[4][4], bh[4][2];                                      \
            _Pragma("unroll")                                                 \
            for (int mf = 0; mf < 4; mf++) {                                  \
                uint32_t off = arow + mf * 2048 + kofs;                       \
                off ^= (off >> 3) & 0x70;                                     \
                ldsm4(ah[mf], st + off);                                      \
            }                                                                 \
            _Pragma("unroll")                                                 \
            for (int gg = 0; gg < 2; gg++) {                                  \
                uint32_t off = brow + gg * 2048 + kofs;                       \
                off ^= (off >> 3) & 0x70;                                     \
                uint32_t qq[4];                                               \
                ldsm4(qq, st + OFF_B + off);                                  \
                bh[gg * 2][0] = qq[0]; bh[gg * 2][1] = qq[2];                 \
                bh[gg * 2 + 1][0] = qq[1]; bh[gg * 2 + 1][1] = qq[3];         \
            }                                                                 \
            _Pragma("unroll")                                                 \
            for (int mf = 0; mf < 4; mf++)                                    \
                _Pragma("unroll")                                             \
                for (int nf = 0; nf < 4; nf++)                                \
                    mma16816(acc[mf][nf], ah[mf], bh[nf]);                    \
        }                                                                     \
    }

// ======== fused attention kernel: z<12 -> kv+reductions, z>=12 -> q+attn ====
__global__ void __launch_bounds__(256, 2)
gemm_fused(const __half* __restrict__ A, const __half* __restrict__ Wq,
           const float* __restrict__ y, float* __restrict__ red,
           int* __restrict__ cnt,
           __half* __restrict__ oL, __half* __restrict__ oG)
{
    extern __shared__ char smraw[];
    const uint32_t sbase = (smem_u32(smraw) + 1023u) & ~1023u;
    const int tid = threadIdx.x;
    const int lane = tid & 31, wid = tid >> 5;
    const int warp_m = wid >> 2, warp_n = wid & 3;
    const int m0 = blockIdx.x * BMt;
    const int b = m0 >> 12;
    const int z = blockIdx.z;
    const bool is_kv = (z < 12);

    float acc[4][4][4];
#pragma unroll
    for (int i = 0; i < 4; i++)
#pragma unroll
        for (int j = 0; j < 4; j++)
#pragma unroll
            for (int e = 0; e < 4; e++) acc[i][j][e] = 0.0f;

    if (is_kv) {
        const int g64 = z * 64;
        auto load_tile = [&](int kt, int s) {
            const uint32_t st = sbase + s * STG;
            const int kb = kt * BKt;
#pragma unroll
            for (int i = tid; i < 1024; i += 256) {
                const int r = i >> 3, cc = i & 7;
                uint32_t off = (uint32_t)(r * 128 + cc * 16);
                off ^= (off >> 3) & 0x70;
                cp16(st + off, A + (size_t)(m0 + r) * KDIM + kb + cc * 8);
                const int rg = (r < 64) ? (CH + g64 + r) : (2 * CH + g64 + r - 64);
                cp16(st + OFF_B + off, Wq + (size_t)rg * KDIM + kb + cc * 8);
            }
            CP_COMMIT();
        };

        GEMM_MAINLOOP(load_tile)

        __syncthreads();
        float* vbuf = reinterpret_cast<float*>(smraw); // [128][65]
        const bool is_v = (warp_n >= 2);

        if (is_v) {
#pragma unroll
            for (int mf = 0; mf < 4; mf++) {
                const int r = warp_m * 64 + mf * 16 + (lane >> 2);
#pragma unroll
                for (int nf = 0; nf < 4; nf++) {
                    const int cl = (warp_n - 2) * 32 + nf * 8 + (lane & 3) * 2;
                    vbuf[r * 65 + cl]           = acc[mf][nf][0];
                    vbuf[r * 65 + cl + 1]       = acc[mf][nf][1];
                    vbuf[(r + 8) * 65 + cl]     = acc[mf][nf][2];
                    vbuf[(r + 8) * 65 + cl + 1] = acc[mf][nf][3];
                }
            }
        }
        __syncthreads();

        if (is_v) {
            float s0[4], s1[4];
#pragma unroll
            for (int nf = 0; nf < 4; nf++) { s0[nf] = 0.f; s1[nf] = 0.f; }
#pragma unroll
            for (int mf = 0; mf < 4; mf++) {
                const int r = m0 + warp_m * 64 + mf * 16 + (lane >> 2);
#pragma unroll
                for (int nf = 0; nf < 4; nf++) {
                    const int cg = g64 + (warp_n - 2) * 32 + nf * 8 + (lane & 3) * 2;
                    const float2 ya = *reinterpret_cast<const float2*>(y + (size_t)r * CH + cg);
                    const float2 yb = *reinterpret_cast<const float2*>(y + (size_t)(r + 8) * CH + cg);
                    s0[nf] = fmaf(delu_f(ya.x), acc[mf][nf][0], s0[nf]);
                    s1[nf] = fmaf(delu_f(ya.y), acc[mf][nf][1], s1[nf]);
                    s0[nf] = fmaf(delu_f(yb.x), acc[mf][nf][2], s0[nf]);
                    s1[nf] = fmaf(delu_f(yb.y), acc[mf][nf][3], s1[nf]);
                }
            }
#pragma unroll
            for (int nf = 0; nf < 4; nf++) {
#pragma unroll
                for (int off = 4; off <= 16; off <<= 1) {
                    s0[nf] += __shfl_xor_sync(0xffffffffu, s0[nf], off);
                    s1[nf] += __shfl_xor_sync(0xffffffffu, s1[nf], off);
                }
            }
            if (lane < 4) {
#pragma unroll
                for (int nf = 0; nf < 4; nf++) {
                    const int cg = g64 + (warp_n - 2) * 32 + nf * 8 + lane * 2;
                    atomicAdd(&red[BATCH * CH + b * CH + cg],     s0[nf]);
                    atomicAdd(&red[BATCH * CH + b * CH + cg + 1], s1[nf]);
                }
            }
        } else {
            float p0[4], p1[4], k0[4], k1[4];
#pragma unroll
            for (int nf = 0; nf < 4; nf++) { p0[nf] = p1[nf] = k0[nf] = k1[nf] = 0.f; }
#pragma unroll
            for (int mf = 0; mf < 4; mf++) {
                const int r = warp_m * 64 + mf * 16 + (lane >> 2);
#pragma unroll
                for (int nf = 0; nf < 4; nf++) {
                    const int cl = warp_n * 32 + nf * 8 + (lane & 3) * 2;
                    const float ka = delu_f(acc[mf][nf][0]);
                    const float kb = delu_f(acc[mf][nf][1]);
                    const float kc = delu_f(acc[mf][nf][2]);
                    const float kd = delu_f(acc[mf][nf][3]);
                    p0[nf] = fmaf(ka, vbuf[r * 65 + cl],           p0[nf]);
                    p1[nf] = fmaf(kb, vbuf[r * 65 + cl + 1],       p1[nf]);
                    p0[nf] = fmaf(kc, vbuf[(r + 8) * 65 + cl],     p0[nf]);
                    p1[nf] = fmaf(kd, vbuf[(r + 8) * 65 + cl + 1], p1[nf]);
                    k0[nf] += ka + kc;
                    k1[nf] += kb + kd;
                }
            }
#pragma unroll
            for (int nf = 0; nf < 4; nf++) {
#pragma unroll
                for (int off = 4; off <= 16; off <<= 1) {
                    p0[nf] += __shfl_xor_sync(0xffffffffu, p0[nf], off);
                    p1[nf] += __shfl_xor_sync(0xffffffffu, p1[nf], off);
                    k0[nf] += __shfl_xor_sync(0xffffffffu, k0[nf], off);
                    k1[nf] += __shfl_xor_sync(0xffffffffu, k1[nf], off);
                }
            }
            if (lane < 4) {
#pragma unroll
                for (int nf = 0; nf < 4; nf++) {
                    const int cg = g64 + warp_n * 32 + nf * 8 + lane * 2;
                    atomicAdd(&red[b * CH + cg],     p0[nf]);
                    atomicAdd(&red[b * CH + cg + 1], p1[nf]);
                    atomicAdd(&red[2 * BATCH * CH + b * CH + cg],     k0[nf]);
                    atomicAdd(&red[2 * BATCH * CH + b * CH + cg + 1], k1[nf]);
                }
            }
        }
        // release: publish this CTA's contributions
        __syncthreads();
        if (tid == 0) {
            __threadfence();
            atomicAdd(cnt, 1);
        }
    } else {
        // ---- q path ----
        const int n0 = (z - 12) * BNt;
        auto load_tile = [&](int kt, int s) {
            const uint32_t st = sbase + s * STG;
            const int kb = kt * BKt;
#pragma unroll
            for (int i = tid; i < 1024; i += 256) {
                const int r = i >> 3, cc = i & 7;
                uint32_t off = (uint32_t)(r * 128 + cc * 16);
                off ^= (off >> 3) & 0x70;
                cp16(st + off,         A + (size_t)(m0 + r) * KDIM + kb + cc * 8);
                cp16(st + OFF_B + off, Wq + (size_t)(n0 + r) * KDIM + kb + cc * 8);
            }
            CP_COMMIT();
        };

        GEMM_MAINLOOP(load_tile)

        // acquire: wait for all kv CTAs
        if (tid == 0) {
            while (*reinterpret_cast<volatile int*>(cnt) < KV_CTAS) { }
            __threadfence();
        }
        __syncthreads();

        const float* ksb  = red + 2 * BATCH * CH + b * CH;
        const float* kvb  = red + b * CH;
        const float* lkvb = red + BATCH * CH + b * CH;

        float ks0[4], ks1[4], kv0[4], kv1[4], lk0[4], lk1[4];
#pragma unroll
        for (int nf = 0; nf < 4; nf++) {
            const int col = n0 + warp_n * 32 + nf * 8 + (lane & 3) * 2;
            ks0[nf] = ksb[col] + EPSV;       ks1[nf] = ksb[col + 1] + EPSV;
            kv0[nf] = kvb[col] * SCALE;      kv1[nf] = kvb[col + 1] * SCALE;
            lk0[nf] = lkvb[col] * SCALE;     lk1[nf] = lkvb[col + 1] * SCALE;
        }

#pragma unroll
        for (int mf = 0; mf < 4; mf++)
#pragma unroll
            for (int nf = 0; nf < 4; nf++)
#pragma unroll
                for (int e = 0; e < 4; e++) acc[mf][nf][e] = delu_f(acc[mf][nf][e]);

        float (*psum)[128] = reinterpret_cast<float (*)[128]>(smraw); // [4][128]

#pragma unroll
        for (int mf = 0; mf < 4; mf++) {
            float pa = 0.f, pb = 0.f;
#pragma unroll
            for (int nf = 0; nf < 4; nf++) {
                pa += acc[mf][nf][0] * ks0[nf] + acc[mf][nf][1] * ks1[nf];
                pb += acc[mf][nf][2] * ks0[nf] + acc[mf][nf][3] * ks1[nf];
            }
            pa += __shfl_xor_sync(0xffffffffu, pa, 1);
            pa += __shfl_xor_sync(0xffffffffu, pa, 2);
            pb += __shfl_xor_sync(0xffffffffu, pb, 1);
            pb += __shfl_xor_sync(0xffffffffu, pb, 2);
            if ((lane & 3) == 0) {
                const int rl = warp_m * 64 + mf * 16 + (lane >> 2);
                psum[warp_n][rl]     = pa;
                psum[warp_n][rl + 8] = pb;
            }
        }
        __syncthreads();

        const int hw = warp_n & ~1;
#pragma unroll
        for (int mf = 0; mf < 4; mf++) {
            const int rl = warp_m * 64 + mf * 16 + (lane >> 2);
            const float na = ASCALE / (psum[hw][rl]     + psum[hw + 1][rl]);
            const float nb = ASCALE / (psum[hw][rl + 8] + psum[hw + 1][rl + 8]);
            const int row = m0 + rl;
#pragma unroll
            for (int nf = 0; nf < 4; nf++) {
                const int col = n0 + warp_n * 32 + nf * 8 + (lane & 3) * 2;
                const size_t i0 = (size_t)row * CH + col;
                const size_t i1 = (size_t)(row + 8) * CH + col;
                *reinterpret_cast<__half2*>(oL + i0) = __halves2half2(
                    __float2half(acc[mf][nf][0] * kv0[nf] * na),
                    __float2half(acc[mf][nf][1] * kv1[nf] * na));
                *reinterpret_cast<__half2*>(oL + i1) = __halves2half2(
                    __float2half(acc[mf][nf][2] * kv0[nf] * nb),
                    __float2half(acc[mf][nf][3] * kv1[nf] * nb));
                *reinterpret_cast<__half2*>(oG + i0) = __halves2half2(
                    __float2half(acc[mf][nf][0] * lk0[nf] * na),
                    __float2half(acc[mf][nf][1] * lk1[nf] * na));
                *reinterpret_cast<__half2*>(oG + i1) = __halves2half2(
                    __float2half(acc[mf][nf][2] * lk0[nf] * nb),
                    __float2half(acc[mf][nf][3] * lk1[nf] * nb));
            }
        }
    }
}

// ======== projection GEMM (both proj in one launch via blockIdx.z) ========
__global__ void __launch_bounds__(256, 2)
gemm_proj(const __half* __restrict__ A, const __half* __restrict__ B,
          const float* __restrict__ bias, float* __restrict__ C,
          const __half* __restrict__ A2, const __half* __restrict__ B2,
          const float* __restrict__ bias2, float* __restrict__ C2)
{
    if (blockIdx.z) { A = A2; B = B2; bias = bias2; C = C2; }

    extern __shared__ char smraw[];
    const uint32_t sbase = (smem_u32(smraw) + 1023u) & ~1023u;
    const int tid = threadIdx.x;
    const int lane = tid & 31, wid = tid >> 5;
    const int warp_m = wid >> 2, warp_n = wid & 3;
    const int m0 = blockIdx.y * BMt, n0 = blockIdx.x * BNt;

    float acc[4][4][4];
#pragma unroll
    for (int i = 0; i < 4; i++)
#pragma unroll
        for (int j = 0; j < 4; j++)
#pragma unroll
            for (int e = 0; e < 4; e++) acc[i][j][e] = 0.0f;

    auto load_tile = [&](int kt, int s) {
        const uint32_t st = sbase + s * STG;
        const int kb = kt * BKt;
#pragma unroll
        for (int i = tid; i < 1024; i += 256) {
            const int r = i >> 3, cc = i & 7;
            uint32_t off = (uint32_t)(r * 128 + cc * 16);
            off ^= (off >> 3) & 0x70;
            cp16(st + off,         A + (size_t)(m0 + r) * KDIM + kb + cc * 8);
            cp16(st + OFF_B + off, B + (size_t)(n0 + r) * KDIM + kb + cc * 8);
        }
        CP_COMMIT();
    };

    GEMM_MAINLOOP(load_tile)

#pragma unroll
    for (int mf = 0; mf < 4; mf++) {
        const int row = m0 + warp_m * 64 + mf * 16 + (lane >> 2);
#pragma unroll
        for (int nf = 0; nf < 4; nf++) {
            const int col = n0 + warp_n * 32 + nf * 8 + (lane & 3) * 2;
            const float b0 = bias[col], b1 = bias[col + 1];
            float v0 = fmaf(acc[mf][nf][0], INV_ASCALE, b0);
            float v1 = fmaf(acc[mf][nf][1], INV_ASCALE, b1);
            float v2 = fmaf(acc[mf][nf][2], INV_ASCALE, b0);
            float v3 = fmaf(acc[mf][nf][3], INV_ASCALE, b1);
            float2* p0 = reinterpret_cast<float2*>(C + (size_t)row * CH + col);
            float2* p1 = reinterpret_cast<float2*>(C + (size_t)(row + 8) * CH + col);
            *p0 = make_float2(v0, v1);
            *p1 = make_float2(v2, v3);
        }
    }
}

// ---------------- fused f32 -> fp16 convert (4 segments) + zero ------------
#define SEG0 (M_ROWS * CH)            // x
#define SEG1 (QKV_N * CH)             // qkv_w
#define SEG2 (CH * CH)                // proj1_w
#define SEG3 (CH * CH)                // proj2_w
#define CONV_TOTAL (SEG0 + SEG1 + SEG2 + SEG3)

__global__ void conv_all_kernel(const float* __restrict__ x,  __half* __restrict__ dx,
                                const float* __restrict__ w0, __half* __restrict__ d0,
                                const float* __restrict__ w1, __half* __restrict__ d1,
                                const float* __restrict__ w2, __half* __restrict__ d2,
                                float* __restrict__ red, int* __restrict__ cnt)
{
    const int gt = blockIdx.x * blockDim.x + threadIdx.x;
    if (gt == 0) *cnt = 0;
    if (gt < 3 * BATCH * CH) red[gt] = 0.0f;

    int i = gt * 4;
    const float* src; __half* dst;
    if (i < SEG0)                      { src = x;  dst = dx; }
    else if ((i -= SEG0) < SEG1)       { src = w0; dst = d0; }
    else if ((i -= SEG1) < SEG2)       { src = w1; dst = d1; }
    else if ((i -= SEG2) < SEG3)       { src = w2; dst = d2; }
    else return;

    float4 v = *reinterpret_cast<const float4*>(src + i);
    __half2* D = reinterpret_cast<__half2*>(dst + i);
    D[0] = __halves2half2(__float2half(v.x), __float2half(v.y));
    D[1] = __halves2half2(__float2half(v.z), __float2half(v.w));
}

// ---------------- launch ----------------
extern "C" void kernel_launch(void* const* d_in, const int* in_sizes, int n_in,
                              void* d_out, int out_size)
{
    const float* x       = (const float*)d_in[0];
    const float* y       = (const float*)d_in[1];
    const float* qkv_w   = (const float*)d_in[2];
    const float* proj1_w = (const float*)d_in[3];
    const float* proj1_b = (const float*)d_in[4];
    const float* proj2_w = (const float*)d_in[5];
    const float* proj2_b = (const float*)d_in[6];
    float* out = (float*)d_out;

    float* red_p;
    int* cnt_p;
    __half *x16, *wq, *w1, *w2, *aL, *aG;
    cudaGetSymbolAddress((void**)&red_p, g_red);
    cudaGetSymbolAddress((void**)&cnt_p, g_cnt);
    cudaGetSymbolAddress((void**)&x16, g_x16);
    cudaGetSymbolAddress((void**)&wq, g_wq);
    cudaGetSymbolAddress((void**)&w1, g_w1);   cudaGetSymbolAddress((void**)&w2, g_w2);
    cudaGetSymbolAddress((void**)&aL, g_aL);   cudaGetSymbolAddress((void**)&aG, g_aG);

    cudaFuncSetAttribute(gemm_fused,
                         cudaFuncAttributeMaxDynamicSharedMemorySize, GEMM_SMEM);
    cudaFuncSetAttribute(gemm_proj,
                         cudaFuncAttributeMaxDynamicSharedMemorySize, GEMM_SMEM);

    // 0) one conversion kernel: x + 3 weights -> fp16, zero red + counter
    conv_all_kernel<<<(CONV_TOTAL / 4 + 255) / 256, 256>>>(
        x, x16, qkv_w, wq, proj1_w, w1, proj2_w, w2, red_p, cnt_p);

    // 1) fused attention: kv+reductions (z<12) and q+attn (z>=12, spin on cnt)
    {
        dim3 grid(M_ROWS / BMt, 1, 18);
        gemm_fused<<<grid, 256, GEMM_SMEM>>>(x16, wq, y, red_p, cnt_p, aL, aG);
    }

    // 2) both output projections in ONE launch (blockIdx.z selects)
    {
        dim3 grid(CH / BNt, M_ROWS / BMt, 2);
        gemm_proj<<<grid, 256, GEMM_SMEM>>>(
            aL, w1, proj1_b, out,
            aG, w2, proj2_b, out + BNC);
    }
}

// round 13
// speedup vs baseline: 7.7134x; 1.0294x over previous
#include <cuda_runtime.h>
#include <cuda_fp16.h>
#include <cstdint>
#include <math.h>

// ---------------- problem constants ----------------
#define BATCH 4
#define SEQ   4096
#define CH    768
#define NHEAD 12
#define HDIM  64
#define M_ROWS (BATCH * SEQ)          // 16384
#define QKV_N  (3 * CH)               // 2304
#define BNC   (M_ROWS * CH)
#define SCALE 0.125f
#define EPSV  1e-10f
#define KDIM  768
#define ASCALE 4096.0f
#define INV_ASCALE (1.0f / 4096.0f)
#define KV_CTAS 1536                  // 12 * 128
#define NMT 128                       // number of m tiles

// ---------------- scratch (device globals) ----------------
__device__ __half g_x16[M_ROWS * CH];
__device__ __half g_wq[QKV_N * CH];
__device__ __half g_w1[CH * CH], g_w2[CH * CH];
__device__ __half g_aL[M_ROWS * CH];
__device__ __half g_aG[M_ROWS * CH];
__device__ float g_red[3 * BATCH * CH];       // [kv | lkv | ksum]
__device__ int   g_cnt[1 + NMT];              // [0]=kv count, [1+mt]=q count per m-tile

// ---------------- helpers ----------------
__device__ __forceinline__ float delu_f(float x) {
    return (x >= 0.0f) ? fmaf(10.0f, x, 1.0f) : __expf(10.0f * x);
}

__device__ __forceinline__ uint32_t smem_u32(const void* p) {
    uint32_t a;
    asm("{ .reg .u64 t; cvta.to.shared.u64 t, %1; cvt.u32.u64 %0, t; }" : "=r"(a) : "l"(p));
    return a;
}

__device__ __forceinline__ void cp16(uint32_t s, const void* g) {
    asm volatile("cp.async.cg.shared.global [%0], [%1], 16;" :: "r"(s), "l"(g));
}
#define CP_COMMIT() asm volatile("cp.async.commit_group;" ::: "memory")

__device__ __forceinline__ void ldsm4(uint32_t* r, uint32_t a) {
    asm volatile("ldmatrix.sync.aligned.m8n8.x4.shared.b16 {%0,%1,%2,%3}, [%4];"
                 : "=r"(r[0]), "=r"(r[1]), "=r"(r[2]), "=r"(r[3]) : "r"(a));
}

__device__ __forceinline__ void mma16816(float* c, const uint32_t* a, const uint32_t* b) {
    asm volatile(
        "mma.sync.aligned.m16n8k16.row.col.f32.f16.f16.f32 "
        "{%0,%1,%2,%3},{%4,%5,%6,%7},{%8,%9},{%0,%1,%2,%3};"
        : "+f"(c[0]), "+f"(c[1]), "+f"(c[2]), "+f"(c[3])
        : "r"(a[0]), "r"(a[1]), "r"(a[2]), "r"(a[3]), "r"(b[0]), "r"(b[1]));
}

// ---------------- tiling ----------------
#define BMt 128
#define BNt 128
#define BKt 64
#define NKT (KDIM / BKt)             // 12
#define TILE_B 16384
#define OFF_B TILE_B
#define STG (2 * TILE_B)             // 32 KB per stage
#define NSTG 3
#define GEMM_SMEM (NSTG * STG + 1024)

#define GEMM_MAINLOOP(LOADFN)                                                 \
    LOADFN(0, 0);                                                             \
    LOADFN(1, 1);                                                             \
    const uint32_t arow = (uint32_t)((warp_m * 64 + (lane & 15)) * 128 + (lane >> 4) * 16); \
    const uint32_t brow = (uint32_t)((warp_n * 32 + (lane & 15)) * 128 + (lane >> 4) * 16); \
    for (int c = 0; c < NKT; c++) {                                           \
        const int s = c % NSTG;                                               \
        if (c == NKT - 1) asm volatile("cp.async.wait_group 0;" ::: "memory");\
        else              asm volatile("cp.async.wait_group 1;" ::: "memory");\
        __syncthreads();                                                      \
        if (c + 2 < NKT) LOADFN(c + 2, (c + 2) % NSTG);                       \
        const uint32_t st = sbase + s * STG;                                  \
        _Pragma("unroll")                                                     \
        for (int ks = 0; ks < 4; ks++) {                                      \
            const uint32_t kofs = ks * 32;                                    \
            uint32_t ah[4][4], bh[4][2];                                      \
            _Pragma("unroll")                                                 \
            for (int mf = 0; mf < 4; mf++) {                                  \
                uint32_t off = arow + mf * 2048 + kofs;                       \
                off ^= (off >> 3) & 0x70;                                     \
                ldsm4(ah[mf], st + off);                                      \
            }                                                                 \
            _Pragma("unroll")                                                 \
            for (int gg = 0; gg < 2; gg++) {                                  \
                uint32_t off = brow + gg * 2048 + kofs;                       \
                off ^= (off >> 3) & 0x70;                                     \
                uint32_t qq[4];                                               \
                ldsm4(qq, st + OFF_B + off);                                  \
                bh[gg * 2][0] = qq[0]; bh[gg * 2][1] = qq[2];                 \
                bh[gg * 2 + 1][0] = qq[1]; bh[gg * 2 + 1][1] = qq[3];         \
            }                                                                 \
            _Pragma("unroll")                                                 \
            for (int mf = 0; mf < 4; mf++)                                    \
                _Pragma("unroll")                                             \
                for (int nf = 0; nf < 4; nf++)                                \
                    mma16816(acc[mf][nf], ah[mf], bh[nf]);                    \
        }                                                                     \
    }

// ======== mega-kernel: z<12 kv+red | z in [12,18) q+attn | z>=18 proj ======
__global__ void __launch_bounds__(256, 2)
gemm_fused(const __half* __restrict__ A, const __half* __restrict__ Wq,
           const float* __restrict__ y, float* __restrict__ red,
           int* __restrict__ cnt,
           __half* __restrict__ oL, __half* __restrict__ oG,
           const __half* __restrict__ w1, const __half* __restrict__ w2,
           const float* __restrict__ b1, const float* __restrict__ b2,
           float* __restrict__ out)
{
    extern __shared__ char smraw[];
    const uint32_t sbase = (smem_u32(smraw) + 1023u) & ~1023u;
    const int tid = threadIdx.x;
    const int lane = tid & 31, wid = tid >> 5;
    const int warp_m = wid >> 2, warp_n = wid & 3;
    const int mt = blockIdx.x;
    const int m0 = mt * BMt;
    const int b = m0 >> 12;
    const int z = blockIdx.z;

    float acc[4][4][4];
#pragma unroll
    for (int i = 0; i < 4; i++)
#pragma unroll
        for (int j = 0; j < 4; j++)
#pragma unroll
            for (int e = 0; e < 4; e++) acc[i][j][e] = 0.0f;

    if (z < 12) {
        // ================= kv + diagonal reductions =================
        const int g64 = z * 64;
        auto load_tile = [&](int kt, int s) {
            const uint32_t st = sbase + s * STG;
            const int kb = kt * BKt;
#pragma unroll
            for (int i = tid; i < 1024; i += 256) {
                const int r = i >> 3, cc = i & 7;
                uint32_t off = (uint32_t)(r * 128 + cc * 16);
                off ^= (off >> 3) & 0x70;
                cp16(st + off, A + (size_t)(m0 + r) * KDIM + kb + cc * 8);
                const int rg = (r < 64) ? (CH + g64 + r) : (2 * CH + g64 + r - 64);
                cp16(st + OFF_B + off, Wq + (size_t)rg * KDIM + kb + cc * 8);
            }
            CP_COMMIT();
        };

        GEMM_MAINLOOP(load_tile)

        __syncthreads();
        float* vbuf = reinterpret_cast<float*>(smraw); // [128][65]
        const bool is_v = (warp_n >= 2);

        if (is_v) {
#pragma unroll
            for (int mf = 0; mf < 4; mf++) {
                const int r = warp_m * 64 + mf * 16 + (lane >> 2);
#pragma unroll
                for (int nf = 0; nf < 4; nf++) {
                    const int cl = (warp_n - 2) * 32 + nf * 8 + (lane & 3) * 2;
                    vbuf[r * 65 + cl]           = acc[mf][nf][0];
                    vbuf[r * 65 + cl + 1]       = acc[mf][nf][1];
                    vbuf[(r + 8) * 65 + cl]     = acc[mf][nf][2];
                    vbuf[(r + 8) * 65 + cl + 1] = acc[mf][nf][3];
                }
            }
        }
        __syncthreads();

        if (is_v) {
            float s0[4], s1[4];
#pragma unroll
            for (int nf = 0; nf < 4; nf++) { s0[nf] = 0.f; s1[nf] = 0.f; }
#pragma unroll
            for (int mf = 0; mf < 4; mf++) {
                const int r = m0 + warp_m * 64 + mf * 16 + (lane >> 2);
#pragma unroll
                for (int nf = 0; nf < 4; nf++) {
                    const int cg = g64 + (warp_n - 2) * 32 + nf * 8 + (lane & 3) * 2;
                    const float2 ya = *reinterpret_cast<const float2*>(y + (size_t)r * CH + cg);
                    const float2 yb = *reinterpret_cast<const float2*>(y + (size_t)(r + 8) * CH + cg);
                    s0[nf] = fmaf(delu_f(ya.x), acc[mf][nf][0], s0[nf]);
                    s1[nf] = fmaf(delu_f(ya.y), acc[mf][nf][1], s1[nf]);
                    s0[nf] = fmaf(delu_f(yb.x), acc[mf][nf][2], s0[nf]);
                    s1[nf] = fmaf(delu_f(yb.y), acc[mf][nf][3], s1[nf]);
                }
            }
#pragma unroll
            for (int nf = 0; nf < 4; nf++) {
#pragma unroll
                for (int off = 4; off <= 16; off <<= 1) {
                    s0[nf] += __shfl_xor_sync(0xffffffffu, s0[nf], off);
                    s1[nf] += __shfl_xor_sync(0xffffffffu, s1[nf], off);
                }
            }
            if (lane < 4) {
#pragma unroll
                for (int nf = 0; nf < 4; nf++) {
                    const int cg = g64 + (warp_n - 2) * 32 + nf * 8 + lane * 2;
                    atomicAdd(&red[BATCH * CH + b * CH + cg],     s0[nf]);
                    atomicAdd(&red[BATCH * CH + b * CH + cg + 1], s1[nf]);
                }
            }
        } else {
            float p0[4], p1[4], k0[4], k1[4];
#pragma unroll
            for (int nf = 0; nf < 4; nf++) { p0[nf] = p1[nf] = k0[nf] = k1[nf] = 0.f; }
#pragma unroll
            for (int mf = 0; mf < 4; mf++) {
                const int r = warp_m * 64 + mf * 16 + (lane >> 2);
#pragma unroll
                for (int nf = 0; nf < 4; nf++) {
                    const int cl = warp_n * 32 + nf * 8 + (lane & 3) * 2;
                    const float ka = delu_f(acc[mf][nf][0]);
                    const float kb = delu_f(acc[mf][nf][1]);
                    const float kc = delu_f(acc[mf][nf][2]);
                    const float kd = delu_f(acc[mf][nf][3]);
                    p0[nf] = fmaf(ka, vbuf[r * 65 + cl],           p0[nf]);
                    p1[nf] = fmaf(kb, vbuf[r * 65 + cl + 1],       p1[nf]);
                    p0[nf] = fmaf(kc, vbuf[(r + 8) * 65 + cl],     p0[nf]);
                    p1[nf] = fmaf(kd, vbuf[(r + 8) * 65 + cl + 1], p1[nf]);
                    k0[nf] += ka + kc;
                    k1[nf] += kb + kd;
                }
            }
#pragma unroll
            for (int nf = 0; nf < 4; nf++) {
#pragma unroll
                for (int off = 4; off <= 16; off <<= 1) {
                    p0[nf] += __shfl_xor_sync(0xffffffffu, p0[nf], off);
                    p1[nf] += __shfl_xor_sync(0xffffffffu, p1[nf], off);
                    k0[nf] += __shfl_xor_sync(0xffffffffu, k0[nf], off);
                    k1[nf] += __shfl_xor_sync(0xffffffffu, k1[nf], off);
                }
            }
            if (lane < 4) {
#pragma unroll
                for (int nf = 0; nf < 4; nf++) {
                    const int cg = g64 + warp_n * 32 + nf * 8 + lane * 2;
                    atomicAdd(&red[b * CH + cg],     p0[nf]);
                    atomicAdd(&red[b * CH + cg + 1], p1[nf]);
                    atomicAdd(&red[2 * BATCH * CH + b * CH + cg],     k0[nf]);
                    atomicAdd(&red[2 * BATCH * CH + b * CH + cg + 1], k1[nf]);
                }
            }
        }
        __syncthreads();
        if (tid == 0) {
            __threadfence();
            atomicAdd(&cnt[0], 1);
        }
    } else if (z < 18) {
        // ================= q GEMM + norm + attention =================
        const int n0 = (z - 12) * BNt;
        auto load_tile = [&](int kt, int s) {
            const uint32_t st = sbase + s * STG;
            const int kb = kt * BKt;
#pragma unroll
            for (int i = tid; i < 1024; i += 256) {
                const int r = i >> 3, cc = i & 7;
                uint32_t off = (uint32_t)(r * 128 + cc * 16);
                off ^= (off >> 3) & 0x70;
                cp16(st + off,         A + (size_t)(m0 + r) * KDIM + kb + cc * 8);
                cp16(st + OFF_B + off, Wq + (size_t)(n0 + r) * KDIM + kb + cc * 8);
            }
            CP_COMMIT();
        };

        GEMM_MAINLOOP(load_tile)

        // acquire: all kv CTAs done
        if (tid == 0) {
            while (*reinterpret_cast<volatile int*>(&cnt[0]) < KV_CTAS) { }
            __threadfence();
        }
        __syncthreads();

        const float* ksb  = red + 2 * BATCH * CH + b * CH;
        const float* kvb  = red + b * CH;
        const float* lkvb = red + BATCH * CH + b * CH;

        float ks0[4], ks1[4], kv0[4], kv1[4], lk0[4], lk1[4];
#pragma unroll
        for (int nf = 0; nf < 4; nf++) {
            const int col = n0 + warp_n * 32 + nf * 8 + (lane & 3) * 2;
            ks0[nf] = ksb[col] + EPSV;       ks1[nf] = ksb[col + 1] + EPSV;
            kv0[nf] = kvb[col] * SCALE;      kv1[nf] = kvb[col + 1] * SCALE;
            lk0[nf] = lkvb[col] * SCALE;     lk1[nf] = lkvb[col + 1] * SCALE;
        }

#pragma unroll
        for (int mf = 0; mf < 4; mf++)
#pragma unroll
            for (int nf = 0; nf < 4; nf++)
#pragma unroll
                for (int e = 0; e < 4; e++) acc[mf][nf][e] = delu_f(acc[mf][nf][e]);

        float (*psum)[128] = reinterpret_cast<float (*)[128]>(smraw); // [4][128]

#pragma unroll
        for (int mf = 0; mf < 4; mf++) {
            float pa = 0.f, pb = 0.f;
#pragma unroll
            for (int nf = 0; nf < 4; nf++) {
                pa += acc[mf][nf][0] * ks0[nf] + acc[mf][nf][1] * ks1[nf];
                pb += acc[mf][nf][2] * ks0[nf] + acc[mf][nf][3] * ks1[nf];
            }
            pa += __shfl_xor_sync(0xffffffffu, pa, 1);
            pa += __shfl_xor_sync(0xffffffffu, pa, 2);
            pb += __shfl_xor_sync(0xffffffffu, pb, 1);
            pb += __shfl_xor_sync(0xffffffffu, pb, 2);
            if ((lane & 3) == 0) {
                const int rl = warp_m * 64 + mf * 16 + (lane >> 2);
                psum[warp_n][rl]     = pa;
                psum[warp_n][rl + 8] = pb;
            }
        }
        __syncthreads();

        const int hw = warp_n & ~1;
#pragma unroll
        for (int mf = 0; mf < 4; mf++) {
            const int rl = warp_m * 64 + mf * 16 + (lane >> 2);
            const float na = ASCALE / (psum[hw][rl]     + psum[hw + 1][rl]);
            const float nb = ASCALE / (psum[hw][rl + 8] + psum[hw + 1][rl + 8]);
            const int row = m0 + rl;
#pragma unroll
            for (int nf = 0; nf < 4; nf++) {
                const int col = n0 + warp_n * 32 + nf * 8 + (lane & 3) * 2;
                const size_t i0 = (size_t)row * CH + col;
                const size_t i1 = (size_t)(row + 8) * CH + col;
                *reinterpret_cast<__half2*>(oL + i0) = __halves2half2(
                    __float2half(acc[mf][nf][0] * kv0[nf] * na),
                    __float2half(acc[mf][nf][1] * kv1[nf] * na));
                *reinterpret_cast<__half2*>(oL + i1) = __halves2half2(
                    __float2half(acc[mf][nf][2] * kv0[nf] * nb),
                    __float2half(acc[mf][nf][3] * kv1[nf] * nb));
                *reinterpret_cast<__half2*>(oG + i0) = __halves2half2(
                    __float2half(acc[mf][nf][0] * lk0[nf] * na),
                    __float2half(acc[mf][nf][1] * lk1[nf] * na));
                *reinterpret_cast<__half2*>(oG + i1) = __halves2half2(
                    __float2half(acc[mf][nf][2] * lk0[nf] * nb),
                    __float2half(acc[mf][nf][3] * lk1[nf] * nb));
            }
        }
        // release this m-tile for projections
        __syncthreads();
        if (tid == 0) {
            __threadfence();
            atomicAdd(&cnt[1 + mt], 1);
        }
    } else {
        // ================= projections (z = 18..29) =================
        const int zz = z - 18;
        const int p  = zz / 6;                 // 0 -> proj1, 1 -> proj2
        const int n0 = (zz % 6) * BNt;
        const __half* Ap = p ? oG : oL;
        const __half* Bp = p ? w2 : w1;
        const float* bp  = p ? b2 : b1;
        float* Cp        = out + (size_t)p * BNC;

        // acquire: all 6 q CTAs for this m-tile finished
        if (tid == 0) {
            while (*reinterpret_cast<volatile int*>(&cnt[1 + mt]) < 6) { }
            __threadfence();
        }
        __syncthreads();

        auto load_tile = [&](int kt, int s) {
            const uint32_t st = sbase + s * STG;
            const int kb = kt * BKt;
#pragma unroll
            for (int i = tid; i < 1024; i += 256) {
                const int r = i >> 3, cc = i & 7;
                uint32_t off = (uint32_t)(r * 128 + cc * 16);
                off ^= (off >> 3) & 0x70;
                cp16(st + off,         Ap + (size_t)(m0 + r) * KDIM + kb + cc * 8);
                cp16(st + OFF_B + off, Bp + (size_t)(n0 + r) * KDIM + kb + cc * 8);
            }
            CP_COMMIT();
        };

        GEMM_MAINLOOP(load_tile)

#pragma unroll
        for (int mf = 0; mf < 4; mf++) {
            const int row = m0 + warp_m * 64 + mf * 16 + (lane >> 2);
#pragma unroll
            for (int nf = 0; nf < 4; nf++) {
                const int col = n0 + warp_n * 32 + nf * 8 + (lane & 3) * 2;
                const float bb0 = bp[col], bb1 = bp[col + 1];
                float v0 = fmaf(acc[mf][nf][0], INV_ASCALE, bb0);
                float v1 = fmaf(acc[mf][nf][1], INV_ASCALE, bb1);
                float v2 = fmaf(acc[mf][nf][2], INV_ASCALE, bb0);
                float v3 = fmaf(acc[mf][nf][3], INV_ASCALE, bb1);
                float2* p0 = reinterpret_cast<float2*>(Cp + (size_t)row * CH + col);
                float2* p1 = reinterpret_cast<float2*>(Cp + (size_t)(row + 8) * CH + col);
                *p0 = make_float2(v0, v1);
                *p1 = make_float2(v2, v3);
            }
        }
    }
}

// ---------------- fused f32 -> fp16 convert (4 segments) + zero ------------
#define SEG0 (M_ROWS * CH)            // x
#define SEG1 (QKV_N * CH)             // qkv_w
#define SEG2 (CH * CH)                // proj1_w
#define SEG3 (CH * CH)                // proj2_w
#define CONV_TOTAL (SEG0 + SEG1 + SEG2 + SEG3)

__global__ void conv_all_kernel(const float* __restrict__ x,  __half* __restrict__ dx,
                                const float* __restrict__ w0, __half* __restrict__ d0,
                                const float* __restrict__ w1, __half* __restrict__ d1,
                                const float* __restrict__ w2, __half* __restrict__ d2,
                                float* __restrict__ red, int* __restrict__ cnt)
{
    const int gt = blockIdx.x * blockDim.x + threadIdx.x;
    if (gt < 1 + NMT) cnt[gt] = 0;
    if (gt < 3 * BATCH * CH) red[gt] = 0.0f;

    int i = gt * 4;
    const float* src; __half* dst;
    if (i < SEG0)                      { src = x;  dst = dx; }
    else if ((i -= SEG0) < SEG1)       { src = w0; dst = d0; }
    else if ((i -= SEG1) < SEG2)       { src = w1; dst = d1; }
    else if ((i -= SEG2) < SEG3)       { src = w2; dst = d2; }
    else return;

    float4 v = *reinterpret_cast<const float4*>(src + i);
    __half2* D = reinterpret_cast<__half2*>(dst + i);
    D[0] = __halves2half2(__float2half(v.x), __float2half(v.y));
    D[1] = __halves2half2(__float2half(v.z), __float2half(v.w));
}

// ---------------- launch ----------------
extern "C" void kernel_launch(void* const* d_in, const int* in_sizes, int n_in,
                              void* d_out, int out_size)
{
    const float* x       = (const float*)d_in[0];
    const float* y       = (const float*)d_in[1];
    const float* qkv_w   = (const float*)d_in[2];
    const float* proj1_w = (const float*)d_in[3];
    const float* proj1_b = (const float*)d_in[4];
    const float* proj2_w = (const float*)d_in[5];
    const float* proj2_b = (const float*)d_in[6];
    float* out = (float*)d_out;

    float* red_p;
    int* cnt_p;
    __half *x16, *wq, *w1, *w2, *aL, *aG;
    cudaGetSymbolAddress((void**)&red_p, g_red);
    cudaGetSymbolAddress((void**)&cnt_p, g_cnt);
    cudaGetSymbolAddress((void**)&x16, g_x16);
    cudaGetSymbolAddress((void**)&wq, g_wq);
    cudaGetSymbolAddress((void**)&w1, g_w1);   cudaGetSymbolAddress((void**)&w2, g_w2);
    cudaGetSymbolAddress((void**)&aL, g_aL);   cudaGetSymbolAddress((void**)&aG, g_aG);

    cudaFuncSetAttribute(gemm_fused,
                         cudaFuncAttributeMaxDynamicSharedMemorySize, GEMM_SMEM);

    // 0) one conversion kernel: x + 3 weights -> fp16, zero red + counters
    conv_all_kernel<<<(CONV_TOTAL / 4 + 255) / 256, 256>>>(
        x, x16, qkv_w, wq, proj1_w, w1, proj2_w, w2, red_p, cnt_p);

    // 1) mega-kernel: kv+red (z<12) -> q+attn (z 12..17) -> projections (z 18..29)
    {
        dim3 grid(NMT, 1, 30);
        gemm_fused<<<grid, 256, GEMM_SMEM>>>(
            x16, wq, y, red_p, cnt_p, aL, aG,
            w1, w2, proj1_b, proj2_b, out);
    }
}